// round 12
// baseline (speedup 1.0000x reference)
#include <cuda_runtime.h>
#include <cuda_bf16.h>
#include <math.h>
#include <stdint.h>

#define NN 100000
#define NE 1600000
#define NG 1024
#define FD 128
#define NTILE 782           // ceil(NN/128)
#define NTHR 512

// ===================== scratch (device globals) =====================
__device__ float g_h[NN * FD];      // fp32 h, set 0
__device__ float g_hb[NN * FD];     // fp32 h, set 1
__device__ float g_degf[NN];
__device__ int   g_deg[NN];
__device__ int   g_rowstart[NN + 1];
__device__ int   g_cursor[NN];
__device__ int   g_csrsrc[NE];
__device__ int   g_cnti[NG];
__device__ float g_cntf[NG];
__device__ float g_gm[NG * FD];
__device__ int   g_bsum[256];
// split activations, tile-swizzled (flat cp.async). tail rows stay zero.
__device__ __nv_bfloat16 g_agghi[NTILE * 16384];
__device__ __nv_bfloat16 g_agglo[NTILE * 16384];
__device__ __nv_bfloat16 g_hshi[NTILE * 16384];   // set 0
__device__ __nv_bfloat16 g_hslo[NTILE * 16384];
__device__ __nv_bfloat16 g_hshib[NTILE * 16384];  // set 1
__device__ __nv_bfloat16 g_hslob[NTILE * 16384];
// pre-transposed, split, swizzled weights: 13 matrices of 128x128 bf16
__device__ __nv_bfloat16 g_whi[13 * 16384];
__device__ __nv_bfloat16 g_wlo[13 * 16384];

// ===================== helpers =====================
__device__ __forceinline__ uint32_t smem_u32(const void* p) {
    uint32_t a;
    asm("{ .reg .u64 t; cvta.to.shared.u64 t, %1; cvt.u32.u64 %0, t; }" : "=r"(a) : "l"(p));
    return a;
}

__device__ __forceinline__ uint32_t swoff(int row, int col) {
    return (uint32_t)row * 256u
         + ((uint32_t)(((col >> 3) ^ (row & 7)) & 15) << 4)
         + ((uint32_t)(col & 7) << 1);
}

#define LDM4(r0, r1, r2, r3, a) \
    asm volatile("ldmatrix.sync.aligned.m8n8.x4.shared.b16 {%0,%1,%2,%3}, [%4];" \
        : "=r"(r0), "=r"(r1), "=r"(r2), "=r"(r3) : "r"(a))

#define MMA16(c, a, b0, b1) \
    asm volatile("mma.sync.aligned.m16n8k16.row.col.f32.bf16.bf16.f32 " \
        "{%0,%1,%2,%3},{%4,%5,%6,%7},{%8,%9},{%0,%1,%2,%3};" \
        : "+f"((c)[0]), "+f"((c)[1]), "+f"((c)[2]), "+f"((c)[3]) \
        : "r"((a)[0]), "r"((a)[1]), "r"((a)[2]), "r"((a)[3]), "r"(b0), "r"(b1))

__device__ __forceinline__ void split4(float4 v, uint2& hi, uint2& lo) {
    __nv_bfloat16 hx = __float2bfloat16_rn(v.x), hy = __float2bfloat16_rn(v.y);
    __nv_bfloat16 hz = __float2bfloat16_rn(v.z), hw = __float2bfloat16_rn(v.w);
    float rx = v.x - __bfloat162float(hx), ry = v.y - __bfloat162float(hy);
    float rz = v.z - __bfloat162float(hz), rw = v.w - __bfloat162float(hw);
    __nv_bfloat162 H0; H0.x = hx; H0.y = hy;
    __nv_bfloat162 H1; H1.x = hz; H1.y = hw;
    __nv_bfloat162 L0 = __floats2bfloat162_rn(rx, ry);
    __nv_bfloat162 L1 = __floats2bfloat162_rn(rz, rw);
    hi.x = *(uint32_t*)&H0; hi.y = *(uint32_t*)&H1;
    lo.x = *(uint32_t*)&L0; lo.y = *(uint32_t*)&L1;
}

__device__ __forceinline__ float recon(const char* hi, const char* lo, uint32_t off,
                                       float& v1) {
    uint32_t uh = *(const uint32_t*)(hi + off);
    uint32_t ul = *(const uint32_t*)(lo + off);
    __nv_bfloat162 bh = *(__nv_bfloat162*)&uh;
    __nv_bfloat162 bl = *(__nv_bfloat162*)&ul;
    v1 = __bfloat162float(bh.y) + __bfloat162float(bl.y);
    return __bfloat162float(bh.x) + __bfloat162float(bl.x);
}

__device__ __forceinline__ void conv_tile(const float* __restrict__ src, int nbase,
                                          char* ahi, char* alo) {
#pragma unroll 2
    for (int i = threadIdx.x; i < 4096; i += NTHR) {
        int row = i >> 5, c4 = i & 31;
        int node = nbase + row;
        float4 v = make_float4(0.f, 0.f, 0.f, 0.f);
        if (node < NN) v = ((const float4*)src)[node * 32 + c4];
        uint2 h, l;
        split4(v, h, l);
        uint32_t off = swoff(row, c4 * 4);
        *(uint2*)(ahi + off) = h;
        *(uint2*)(alo + off) = l;
    }
}

__device__ __forceinline__ void copyw(const __nv_bfloat16* src, char* dst) {
    uint32_t d = smem_u32(dst);
    for (int i = threadIdx.x; i < 2048; i += NTHR)
        asm volatile("cp.async.cg.shared.global [%0], [%1], 16;"
                     :: "r"(d + i * 16), "l"(src + i * 8) : "memory");
}
#define CPCOMMIT() asm volatile("cp.async.commit_group;" ::: "memory")
#define CPWAITG(n) asm volatile("cp.async.wait_group %0;" :: "n"(n) : "memory")

__device__ __forceinline__ void gemm3(uint32_t ahi, uint32_t alo,
                                      uint32_t whi, uint32_t wlo,
                                      float C[2][4][4], int lane, int wR, int wC) {
    int arow = (lane & 7) + ((lane >> 3) & 1) * 8;
    int acolo = ((lane >> 4) & 1) * 8;
    int brow = (lane & 7) + ((lane >> 4) & 1) * 8;
    int bcolo = ((lane >> 3) & 1) * 8;
#pragma unroll
    for (int kk = 0; kk < 8; kk++) {
        int kbase = kk * 16;
        uint32_t ah[2][4], al[2][4];
#pragma unroll
        for (int mb = 0; mb < 2; mb++) {
            uint32_t oa = swoff(wR + mb * 16 + arow, kbase + acolo);
            LDM4(ah[mb][0], ah[mb][1], ah[mb][2], ah[mb][3], ahi + oa);
            LDM4(al[mb][0], al[mb][1], al[mb][2], al[mb][3], alo + oa);
        }
#pragma unroll
        for (int nbp = 0; nbp < 2; nbp++) {
            uint32_t ob = swoff(wC + nbp * 16 + brow, kbase + bcolo);
            uint32_t bh[4], bl[4];
            LDM4(bh[0], bh[1], bh[2], bh[3], whi + ob);
            LDM4(bl[0], bl[1], bl[2], bl[3], wlo + ob);
#pragma unroll
            for (int mb = 0; mb < 2; mb++) {
                MMA16(C[mb][2 * nbp],     ah[mb], bh[0], bh[1]);
                MMA16(C[mb][2 * nbp + 1], ah[mb], bh[2], bh[3]);
                MMA16(C[mb][2 * nbp],     ah[mb], bl[0], bl[1]);
                MMA16(C[mb][2 * nbp + 1], ah[mb], bl[2], bl[3]);
                MMA16(C[mb][2 * nbp],     al[mb], bh[0], bh[1]);
                MMA16(C[mb][2 * nbp + 1], al[mb], bh[2], bh[3]);
            }
        }
    }
}

#define ZEROC(C) do { \
    _Pragma("unroll") for (int _a = 0; _a < 2; _a++) \
    _Pragma("unroll") for (int _b = 0; _b < 4; _b++) \
    _Pragma("unroll") for (int _c = 0; _c < 4; _c++) (C)[_a][_b][_c] = 0.f; \
} while (0)

__device__ __forceinline__ void stageC(float* stg, float C[2][4][4], int lane, int wR, int wC) {
    int r0 = wR + (lane >> 2);
    int c0 = wC + (lane & 3) * 2;
#pragma unroll
    for (int mb = 0; mb < 2; mb++) {
#pragma unroll
        for (int nb = 0; nb < 4; nb++) {
            int row = r0 + mb * 16;
            int col = c0 + nb * 8;
            *(float2*)(stg + row * 132 + col) = make_float2(C[mb][nb][0], C[mb][nb][1]);
            *(float2*)(stg + (row + 8) * 132 + col) = make_float2(C[mb][nb][2], C[mb][nb][3]);
        }
    }
}

// ===================== setup kernels =====================
__global__ void k_zero() {
    int i = blockIdx.x * blockDim.x + threadIdx.x;
    if (i < NN) g_deg[i] = 0;
    if (i < NG) g_cnti[i] = 0;
    if (i < NG * FD) g_gm[i] = 0.f;
}
__global__ void k_count(const int* __restrict__ ei, const int* __restrict__ batch) {
    int i = blockIdx.x * blockDim.x + threadIdx.x;
    if (i < NE) atomicAdd(&g_deg[ei[NE + i]], 1);
    if (i < NN) atomicAdd(&g_cnti[batch[i]], 1);
}
__global__ void k_scan1() {
    __shared__ int s[512];
    int i = blockIdx.x * 512 + threadIdx.x;
    int v = (i < NN) ? g_deg[i] : 0;
    s[threadIdx.x] = v;
    __syncthreads();
#pragma unroll
    for (int off = 1; off < 512; off <<= 1) {
        int t = (threadIdx.x >= off) ? s[threadIdx.x - off] : 0;
        __syncthreads();
        s[threadIdx.x] += t;
        __syncthreads();
    }
    if (i < NN) g_rowstart[i + 1] = s[threadIdx.x];
    if (threadIdx.x == 511) g_bsum[blockIdx.x] = s[511];
}
__global__ void k_scan23() {
    __shared__ int pre[256];
    const int nb = (NN + 511) / 512;  // 196
    int v = (threadIdx.x < nb) ? g_bsum[threadIdx.x] : 0;
    pre[threadIdx.x] = v;
    __syncthreads();
#pragma unroll
    for (int off = 1; off < 256; off <<= 1) {
        int t = (threadIdx.x >= off) ? pre[threadIdx.x - off] : 0;
        __syncthreads();
        pre[threadIdx.x] += t;
        __syncthreads();
    }
    pre[threadIdx.x] -= v;  // exclusive
    __syncthreads();
    int i = blockIdx.x * blockDim.x + threadIdx.x;
    if (i >= NN) return;
    int r = g_rowstart[i + 1] + pre[i >> 9];
    g_rowstart[i + 1] = r;
    g_cursor[i] = r - g_deg[i];
    g_degf[i] = fmaxf((float)g_deg[i], 1.f);
    if (i == 0) g_rowstart[0] = 0;
    if (i < NG) g_cntf[i] = fmaxf((float)g_cnti[i], 1.f);
}
__global__ void k_fill(const int* __restrict__ ei) {
    int e = blockIdx.x * blockDim.x + threadIdx.x;
    if (e >= NE) return;
    int src = ei[e];
    int dst = ei[NE + e];
    int pos = atomicAdd(&g_cursor[dst], 1);
    g_csrsrc[pos] = src;
}
// gather over node chunk [nodebase, nodebase+ncnt): fp32 h(flip) -> split agg
__global__ void k_gather(int flip, int nodebase, int ncnt) {
    int gwl = (blockIdx.x * blockDim.x + threadIdx.x) >> 5;
    int lane = threadIdx.x & 31;
    if (gwl >= ncnt) return;
    int gw = nodebase + gwl;
    int beg = g_rowstart[gw], end = g_rowstart[gw + 1];
    float4 acc = make_float4(0.f, 0.f, 0.f, 0.f);
    const float4* hv = (const float4*)(flip ? g_hb : g_h);
    int e = beg;
    for (; e + 4 <= end; e += 4) {
        int s0 = g_csrsrc[e], s1 = g_csrsrc[e + 1], s2 = g_csrsrc[e + 2], s3 = g_csrsrc[e + 3];
        float4 a0 = hv[s0 * 32 + lane];
        float4 a1 = hv[s1 * 32 + lane];
        float4 a2 = hv[s2 * 32 + lane];
        float4 a3 = hv[s3 * 32 + lane];
        acc.x += (a0.x + a1.x) + (a2.x + a3.x);
        acc.y += (a0.y + a1.y) + (a2.y + a3.y);
        acc.z += (a0.z + a1.z) + (a2.z + a3.z);
        acc.w += (a0.w + a1.w) + (a2.w + a3.w);
    }
    for (; e < end; ++e) {
        int s0 = g_csrsrc[e];
        float4 a0 = hv[s0 * 32 + lane];
        acc.x += a0.x; acc.y += a0.y; acc.z += a0.z; acc.w += a0.w;
    }
    float inv = 1.f / g_degf[gw];
    acc.x *= inv; acc.y *= inv; acc.z *= inv; acc.w *= inv;
    uint2 h, l;
    split4(acc, h, l);
    int tile = gw >> 7, row = gw & 127;
    uint32_t off = (uint32_t)tile * 32768u + swoff(row, lane * 4);
    *(uint2*)((char*)g_agghi + off) = h;
    *(uint2*)((char*)g_agglo + off) = l;
}
__global__ void k_wprep(const float* __restrict__ Win, const float* __restrict__ sWl,
                        const float* __restrict__ sWr, const float* __restrict__ l1W,
                        const float* __restrict__ l2W) {
    int m = blockIdx.y;
    int idx = blockIdx.x * 256 + threadIdx.x;
    if (idx >= 16384) return;
    int n = idx >> 7, k = idx & 127;
    float v;
    if (m == 0)       v = Win[k * 128 + n];
    else if (m < 4)   v = sWl[(m - 1) * 16384 + k * 128 + n];
    else if (m < 7)   v = sWr[(m - 4) * 16384 + k * 128 + n];
    else if (m < 10)  v = l1W[(m - 7) * 16384 + k * 128 + n];
    else              v = l2W[(m - 10) * 16384 + k * 128 + n];
    __nv_bfloat16 hi = __float2bfloat16_rn(v);
    float r = v - __bfloat162float(hi);
    __nv_bfloat16 lo = __float2bfloat16_rn(r);
    uint32_t e = swoff(n, k) >> 1;
    g_whi[m * 16384 + e] = hi;
    g_wlo[m * 16384 + e] = lo;
}

// ===================== input GEMM: h = [x|w] @ W_in + b_in (writes set 0) =======
__global__ void __launch_bounds__(NTHR, 1) k_input(
    const float* __restrict__ x, const float* __restrict__ w,
    const float* __restrict__ Win, const float* __restrict__ bin) {
    extern __shared__ char dsm[];
    __shared__ float s_b[128], s_wr[128];
    uint32_t base = smem_u32(dsm);
    uint32_t ab = (base + 1023) & ~1023u;
    char* aptr = dsm + (ab - base);
    int tid = threadIdx.x;
    int lane = tid & 31, wid = tid >> 5;
    int wR = (wid >> 2) * 32, wC = (wid & 3) * 32;
    if (tid < 128) { s_b[tid] = bin[tid]; s_wr[tid] = Win[128 * 128 + tid]; }
    copyw(g_whi, aptr + 65536);
    copyw(g_wlo, aptr + 98304);
    CPCOMMIT();
    int tile = blockIdx.x;
    int nbase = tile * 128;
    conv_tile(x, nbase, aptr, aptr + 32768);
    CPWAITG(0);
    __syncthreads();
    float C[2][4][4];
    ZEROC(C);
    gemm3(ab, ab + 32768, ab + 65536, ab + 98304, C, lane, wR, wC);
    __syncthreads();
    float* stg = (float*)aptr;
    stageC(stg, C, lane, wR, wC);
    __syncthreads();
#pragma unroll 2
    for (int i = tid; i < 4096; i += NTHR) {
        int row = i >> 5, c4 = i & 31;
        int nd = nbase + row;
        if (nd < NN) {
            float wn = w[nd];
            float4 v = ((float4*)(stg + row * 132))[c4];
            float4 o;
            o.x = v.x + s_b[c4 * 4 + 0] + wn * s_wr[c4 * 4 + 0];
            o.y = v.y + s_b[c4 * 4 + 1] + wn * s_wr[c4 * 4 + 1];
            o.z = v.z + s_b[c4 * 4 + 2] + wn * s_wr[c4 * 4 + 2];
            o.w = v.w + s_b[c4 * 4 + 3] + wn * s_wr[c4 * 4 + 3];
            ((float4*)g_h)[nd * 32 + c4] = o;
            uint2 h, l;
            split4(o, h, l);
            uint32_t off = (uint32_t)tile * 32768u + swoff(row, c4 * 4);
            *(uint2*)((char*)g_hshi + off) = h;
            *(uint2*)((char*)g_hslo + off) = l;
        }
    }
}

// ===================== fused sage+FFN block (ping-pong sets, chunked grid) ======
__global__ void __launch_bounds__(NTHR, 1) k_block(
    int flip, int tile0, int wlm, int wrm, int w1m, int w2m, int last,
    const int* __restrict__ batch,
    const float* __restrict__ bl, const float* __restrict__ b1,
    const float* __restrict__ b2,
    const float* __restrict__ g1, const float* __restrict__ e1,
    const float* __restrict__ g2, const float* __restrict__ e2) {
    extern __shared__ char dsm[];
    __shared__ float s_bl[128], s_b1[128], s_b2[128];
    __shared__ float s_g1[128], s_e1[128], s_g2[128], s_e2[128];
    __shared__ float red_s[4][128], red_q[4][128];
    __shared__ int s_batch[128];
    uint32_t base = smem_u32(dsm);
    uint32_t ab = (base + 1023) & ~1023u;
    char* aptr = dsm + (ab - base);
    char* p_ahi = aptr;
    char* p_alo = aptr + 32768;
    char* p_whi = aptr + 65536;
    char* p_wlo = aptr + 98304;
    char* p_yhi = aptr + 131072;
    char* p_ylo = aptr + 163840;
    int tid = threadIdx.x, lane = tid & 31, wid = tid >> 5;
    int wR = (wid >> 2) * 32, wC = (wid & 3) * 32;
    int cg = wid & 3;
    int r0 = wR + (lane >> 2);
    int c0l = (lane & 3) * 2;
    int tile = tile0 + blockIdx.x;
    int nbase = tile * 128;
    const __nv_bfloat16* hs_hi = flip ? g_hshib : g_hshi;
    const __nv_bfloat16* hs_lo = flip ? g_hslob : g_hslo;

    copyw(g_agghi + tile * 16384, p_ahi);
    copyw(g_agglo + tile * 16384, p_alo);
    copyw(g_whi + wlm * 16384, p_whi);
    copyw(g_wlo + wlm * 16384, p_wlo);
    CPCOMMIT();
    copyw(hs_hi + tile * 16384, p_yhi);
    copyw(hs_lo + tile * 16384, p_ylo);
    CPCOMMIT();
    if (tid < 128) {
        s_bl[tid] = bl[tid]; s_b1[tid] = b1[tid]; s_b2[tid] = b2[tid];
        s_g1[tid] = g1[tid]; s_e1[tid] = e1[tid];
        s_g2[tid] = g2[tid]; s_e2[tid] = e2[tid];
        if (last) {
            int nd = nbase + tid;
            s_batch[tid] = (nd < NN) ? batch[nd] : -1;
        }
    }
    CPWAITG(1);
    __syncthreads();

    // ---- sage GEMM 1: agg @ Wl ----
    float C[2][4][4];
    ZEROC(C);
    gemm3(ab, ab + 32768, ab + 65536, ab + 98304, C, lane, wR, wC);
    __syncthreads();

    // ---- sage GEMM 2: h(Y) @ Wr ----
    copyw(g_whi + wrm * 16384, p_whi);
    copyw(g_wlo + wrm * 16384, p_wlo);
    CPCOMMIT();
    CPWAITG(0);
    __syncthreads();
    gemm3(ab + 131072, ab + 163840, ab + 65536, ab + 98304, C, lane, wR, wC);
    __syncthreads();

    copyw(g_whi + w1m * 16384, p_whi);
    copyw(g_wlo + w1m * 16384, p_wlo);
    CPCOMMIT();

    // ---- LN1 (+ h residual from Y split) ----
    {
        float sp[4], qp[4];
#pragma unroll
        for (int mb = 0; mb < 2; mb++)
#pragma unroll
            for (int h = 0; h < 2; h++) {
                int R = r0 + mb * 16 + h * 8;
                float s = 0.f, q = 0.f;
#pragma unroll
                for (int nb = 0; nb < 4; nb++) {
                    int col = wC + c0l + nb * 8;
                    float h1;
                    float h0 = recon(p_yhi, p_ylo, swoff(R, col), h1);
                    float v0 = C[mb][nb][2 * h + 0] + s_bl[col] + h0;
                    float v1 = C[mb][nb][2 * h + 1] + s_bl[col + 1] + h1;
                    C[mb][nb][2 * h + 0] = v0;
                    C[mb][nb][2 * h + 1] = v1;
                    s += v0 + v1;
                    q += v0 * v0 + v1 * v1;
                }
                sp[mb * 2 + h] = s; qp[mb * 2 + h] = q;
            }
#pragma unroll
        for (int k = 0; k < 4; k++) {
            sp[k] += __shfl_xor_sync(0xffffffffu, sp[k], 1);
            sp[k] += __shfl_xor_sync(0xffffffffu, sp[k], 2);
            qp[k] += __shfl_xor_sync(0xffffffffu, qp[k], 1);
            qp[k] += __shfl_xor_sync(0xffffffffu, qp[k], 2);
        }
        if ((lane & 3) == 0) {
#pragma unroll
            for (int k = 0; k < 4; k++) {
                int R = r0 + (k >> 1) * 16 + (k & 1) * 8;
                red_s[cg][R] = sp[k];
                red_q[cg][R] = qp[k];
            }
        }
    }
    __syncthreads();
#pragma unroll
    for (int mb = 0; mb < 2; mb++)
#pragma unroll
        for (int h = 0; h < 2; h++) {
            int R = r0 + mb * 16 + h * 8;
            float S = red_s[0][R] + red_s[1][R] + red_s[2][R] + red_s[3][R];
            float Q = red_q[0][R] + red_q[1][R] + red_q[2][R] + red_q[3][R];
            float mu = S * 0.0078125f;
            float var = Q * 0.0078125f - mu * mu;
            float inv = rsqrtf(var + 1e-5f);
#pragma unroll
            for (int nb = 0; nb < 4; nb++) {
                int col = wC + c0l + nb * 8;
                float y0 = (C[mb][nb][2 * h + 0] - mu) * inv * s_g1[col] + s_e1[col];
                float y1v = (C[mb][nb][2 * h + 1] - mu) * inv * s_g1[col + 1] + s_e1[col + 1];
                __nv_bfloat16 h0 = __float2bfloat16_rn(y0);
                __nv_bfloat16 h1 = __float2bfloat16_rn(y1v);
                __nv_bfloat162 HP; HP.x = h0; HP.y = h1;
                __nv_bfloat162 LP = __floats2bfloat162_rn(y0 - __bfloat162float(h0),
                                                          y1v - __bfloat162float(h1));
                uint32_t off = swoff(R, col);
                *(uint32_t*)(p_ahi + off) = *(uint32_t*)&HP;
                *(uint32_t*)(p_alo + off) = *(uint32_t*)&LP;
            }
        }
    CPWAITG(0);
    __syncthreads();

    // ---- FFN GEMM 1: y1(A) @ W1 ----
    ZEROC(C);
    gemm3(ab, ab + 32768, ab + 65536, ab + 98304, C, lane, wR, wC);
    __syncthreads();

    copyw(g_whi + w2m * 16384, p_whi);
    copyw(g_wlo + w2m * 16384, p_wlo);
    CPCOMMIT();

    // elu(C + b1) -> split into Y
#pragma unroll
    for (int mb = 0; mb < 2; mb++)
#pragma unroll
        for (int nb = 0; nb < 4; nb++) {
            int col = wC + c0l + nb * 8;
#pragma unroll
            for (int h = 0; h < 2; h++) {
                int R = r0 + mb * 16 + h * 8;
                float t0 = C[mb][nb][2 * h + 0] + s_b1[col];
                float t1 = C[mb][nb][2 * h + 1] + s_b1[col + 1];
                t0 = t0 > 0.f ? t0 : (__expf(t0) - 1.f);
                t1 = t1 > 0.f ? t1 : (__expf(t1) - 1.f);
                __nv_bfloat16 h0 = __float2bfloat16_rn(t0);
                __nv_bfloat16 h1 = __float2bfloat16_rn(t1);
                __nv_bfloat162 HP; HP.x = h0; HP.y = h1;
                __nv_bfloat162 LP = __floats2bfloat162_rn(t0 - __bfloat162float(h0),
                                                          t1 - __bfloat162float(h1));
                uint32_t off = swoff(R, col);
                *(uint32_t*)(p_yhi + off) = *(uint32_t*)&HP;
                *(uint32_t*)(p_ylo + off) = *(uint32_t*)&LP;
            }
        }
    CPWAITG(0);
    __syncthreads();

    // ---- FFN GEMM 2: elu(Y) @ W2 ----
    ZEROC(C);
    gemm3(ab + 131072, ab + 163840, ab + 65536, ab + 98304, C, lane, wR, wC);

    // ---- LN2 (+ y1 residual from A split) ----
    {
        float sp[4], qp[4];
#pragma unroll
        for (int mb = 0; mb < 2; mb++)
#pragma unroll
            for (int h = 0; h < 2; h++) {
                int R = r0 + mb * 16 + h * 8;
                float s = 0.f, q = 0.f;
#pragma unroll
                for (int nb = 0; nb < 4; nb++) {
                    int col = wC + c0l + nb * 8;
                    float y1v;
                    float y0 = recon(p_ahi, p_alo, swoff(R, col), y1v);
                    float v0 = C[mb][nb][2 * h + 0] + s_b2[col] + y0;
                    float v1 = C[mb][nb][2 * h + 1] + s_b2[col + 1] + y1v;
                    C[mb][nb][2 * h + 0] = v0;
                    C[mb][nb][2 * h + 1] = v1;
                    s += v0 + v1;
                    q += v0 * v0 + v1 * v1;
                }
                sp[mb * 2 + h] = s; qp[mb * 2 + h] = q;
            }
#pragma unroll
        for (int k = 0; k < 4; k++) {
            sp[k] += __shfl_xor_sync(0xffffffffu, sp[k], 1);
            sp[k] += __shfl_xor_sync(0xffffffffu, sp[k], 2);
            qp[k] += __shfl_xor_sync(0xffffffffu, qp[k], 1);
            qp[k] += __shfl_xor_sync(0xffffffffu, qp[k], 2);
        }
        if ((lane & 3) == 0) {
#pragma unroll
            for (int k = 0; k < 4; k++) {
                int R = r0 + (k >> 1) * 16 + (k & 1) * 8;
                red_s[cg][R] = sp[k];
                red_q[cg][R] = qp[k];
            }
        }
    }
    __syncthreads();
    float* stg = (float*)(aptr + 65536);
#pragma unroll
    for (int mb = 0; mb < 2; mb++)
#pragma unroll
        for (int h = 0; h < 2; h++) {
            int R = r0 + mb * 16 + h * 8;
            float S = red_s[0][R] + red_s[1][R] + red_s[2][R] + red_s[3][R];
            float Q = red_q[0][R] + red_q[1][R] + red_q[2][R] + red_q[3][R];
            float mu = S * 0.0078125f;
            float var = Q * 0.0078125f - mu * mu;
            float inv = rsqrtf(var + 1e-5f);
#pragma unroll
            for (int nb = 0; nb < 4; nb++) {
                int col = wC + c0l + nb * 8;
                float o0 = (C[mb][nb][2 * h + 0] - mu) * inv * s_g2[col] + s_e2[col];
                float o1 = (C[mb][nb][2 * h + 1] - mu) * inv * s_g2[col + 1] + s_e2[col + 1];
                *(float2*)(stg + R * 132 + col) = make_float2(o0, o1);
            }
        }
    __syncthreads();
    if (!last) {
        float* hdst = flip ? g_h : g_hb;
        char* dsthi = (char*)(flip ? g_hshi : g_hshib);
        char* dstlo = (char*)(flip ? g_hslo : g_hslob);
#pragma unroll 2
        for (int i = tid; i < 4096; i += NTHR) {
            int row = i >> 5, c4 = i & 31;
            int nd = nbase + row;
            if (nd < NN) {
                float4 v = ((float4*)(stg + row * 132))[c4];
                ((float4*)hdst)[nd * 32 + c4] = v;
                uint2 h, l;
                split4(v, h, l);
                uint32_t off = (uint32_t)tile * 32768u + swoff(row, c4 * 4);
                *(uint2*)(dsthi + off) = h;
                *(uint2*)(dstlo + off) = l;
            }
        }
    } else {
        int f = tid & 127, q = tid >> 7;
        int rbeg = q * 32;
        int cur = s_batch[rbeg];
        float acc = 0.f;
#pragma unroll 4
        for (int r = rbeg; r < rbeg + 32; r++) {
            int bg = s_batch[r];
            if (bg < 0) break;
            if (bg != cur) {
                atomicAdd(&g_gm[cur * FD + f], acc);
                acc = 0.f;
                cur = bg;
            }
            acc += stg[r * 132 + f];
        }
        if (cur >= 0) atomicAdd(&g_gm[cur * FD + f], acc);
    }
}

// ===================== head =====================
__global__ void __launch_bounds__(128, 1) k_pool(
    const float* __restrict__ mdfW, const float* __restrict__ mdfb,
    const float* __restrict__ pg1, const float* __restrict__ pb1,
    const float* __restrict__ W1, const float* __restrict__ b1,
    const float* __restrict__ W2, const float* __restrict__ b2,
    const float* __restrict__ pg2, const float* __restrict__ pb2,
    float* __restrict__ out) {
    extern __shared__ float ws[];
    __shared__ float vm[128], hh[128], tt[128], red[8];
    int f = threadIdx.x, lane = f & 31, wp = f >> 5;
    for (int i = f; i < 16384; i += 128) {
        ws[i] = mdfW[i];
        ws[16384 + i] = W1[i];
        ws[32768 + i] = W2[i];
    }
    float c_mb = mdfb[f], c_g1 = pg1[f], c_b1 = pb1[f];
    float c_bl1 = b1[f], c_bl2 = b2[f], c_g2 = pg2[f], c_b2 = pb2[f];
    __syncthreads();
    for (int gi = 0; gi < 8; gi++) {
        int g = blockIdx.x * 8 + gi;
        vm[f] = g_gm[g * FD + f] / g_cntf[g];
        __syncthreads();
        float p = 0.f;
#pragma unroll 4
        for (int k = 0; k < 128; k++) p = fmaf(vm[k], ws[k * 128 + f], p);
        p += c_mb;
        float s = p, q = p * p;
#pragma unroll
        for (int off = 16; off; off >>= 1) {
            s += __shfl_xor_sync(0xffffffffu, s, off);
            q += __shfl_xor_sync(0xffffffffu, q, off);
        }
        if (lane == 0) { red[wp] = s; red[4 + wp] = q; }
        __syncthreads();
        s = red[0] + red[1] + red[2] + red[3];
        q = red[4] + red[5] + red[6] + red[7];
        float mu = s * 0.0078125f;
        float var = q * 0.0078125f - mu * mu;
        float inv = rsqrtf(var + 1e-5f);
        float h0 = (p - mu) * inv * c_g1 + c_b1;
        __syncthreads();
        hh[f] = h0;
        __syncthreads();
        float a = 0.f;
#pragma unroll 4
        for (int k = 0; k < 128; k++) a = fmaf(hh[k], ws[16384 + k * 128 + f], a);
        a += c_bl1;
        a = a > 0.f ? a : expm1f(a);
        tt[f] = a;
        __syncthreads();
        float y = 0.f;
#pragma unroll 4
        for (int k = 0; k < 128; k++) y = fmaf(tt[k], ws[32768 + k * 128 + f], y);
        y += c_bl2;
        float v2 = y + h0;
        s = v2; q = v2 * v2;
#pragma unroll
        for (int off = 16; off; off >>= 1) {
            s += __shfl_xor_sync(0xffffffffu, s, off);
            q += __shfl_xor_sync(0xffffffffu, q, off);
        }
        if (lane == 0) { red[wp] = s; red[4 + wp] = q; }
        __syncthreads();
        s = red[0] + red[1] + red[2] + red[3];
        q = red[4] + red[5] + red[6] + red[7];
        mu = s * 0.0078125f;
        var = q * 0.0078125f - mu * mu;
        inv = rsqrtf(var + 1e-5f);
        out[g * FD + f] = (v2 - mu) * inv * c_g2 + c_b2;
        __syncthreads();
    }
}

// ===================== launcher (multi-stream fork/join, capture-legal) ========
extern "C" void kernel_launch(void* const* d_in, const int* in_sizes, int n_in,
                              void* d_out, int out_size) {
    const float* x    = (const float*)d_in[0];
    const float* w    = (const float*)d_in[1];
    const int*   ei   = (const int*)d_in[2];
    const int*   batch= (const int*)d_in[3];
    const float* Win  = (const float*)d_in[4];
    const float* bin  = (const float*)d_in[5];
    const float* sWl  = (const float*)d_in[6];
    const float* sbl  = (const float*)d_in[7];
    const float* sWr  = (const float*)d_in[8];
    const float* ln1g = (const float*)d_in[9];
    const float* ln1b = (const float*)d_in[10];
    const float* l1W  = (const float*)d_in[11];
    const float* l1b  = (const float*)d_in[12];
    const float* l2W  = (const float*)d_in[13];
    const float* l2b  = (const float*)d_in[14];
    const float* ln2g = (const float*)d_in[15];
    const float* ln2b = (const float*)d_in[16];
    const float* mdfW = (const float*)d_in[17];
    const float* mdfb = (const float*)d_in[18];
    const float* pg1  = (const float*)d_in[19];
    const float* pb1  = (const float*)d_in[20];
    const float* pW1  = (const float*)d_in[21];
    const float* pb1l = (const float*)d_in[22];
    const float* pW2  = (const float*)d_in[23];
    const float* pb2l = (const float*)d_in[24];
    const float* pg2  = (const float*)d_in[25];
    const float* pb2  = (const float*)d_in[26];

    const int SM_BLK = 1024 + 196608;
    const int SM_SML = 1024 + 131072;
    const int SM_POOL = 49152 * 4;
    cudaFuncSetAttribute(k_input, cudaFuncAttributeMaxDynamicSharedMemorySize, SM_SML);
    cudaFuncSetAttribute(k_block, cudaFuncAttributeMaxDynamicSharedMemorySize, SM_BLK);
    cudaFuncSetAttribute(k_pool,  cudaFuncAttributeMaxDynamicSharedMemorySize, SM_POOL);

    // chunking: 4 chunks of tiles
    const int NCH = 4;
    const int tb[NCH + 1] = {0, 196, 392, 588, 782};

    cudaStream_t s2;
    cudaStreamCreateWithFlags(&s2, cudaStreamNonBlocking);
    cudaEvent_t evFork, evInput, evLayer[2], evG[3][NCH];
    cudaEventCreateWithFlags(&evFork, cudaEventDisableTiming);
    cudaEventCreateWithFlags(&evInput, cudaEventDisableTiming);
    for (int l = 0; l < 2; l++) cudaEventCreateWithFlags(&evLayer[l], cudaEventDisableTiming);
    for (int l = 0; l < 3; l++)
        for (int c = 0; c < NCH; c++)
            cudaEventCreateWithFlags(&evG[l][c], cudaEventDisableTiming);

    // stream0: zero, then fork
    k_zero<<<512, 256>>>();
    cudaEventRecord(evFork, 0);
    cudaStreamWaitEvent(s2, evFork, 0);

    // s2: CSR build
    k_count<<<(NE + 255) / 256, 256, 0, s2>>>(ei, batch);
    k_scan1<<<(NN + 511) / 512, 512, 0, s2>>>();
    k_scan23<<<(NN + 255) / 256, 256, 0, s2>>>();
    k_fill<<<(NE + 255) / 256, 256, 0, s2>>>(ei);

    // stream0: weights + input GEMM
    k_wprep<<<dim3(64, 13), 256>>>(Win, sWl, sWr, l1W, l2W);
    k_input<<<NTILE, NTHR, SM_SML>>>(x, w, Win, bin);
    cudaEventRecord(evInput, 0);
    cudaStreamWaitEvent(s2, evInput, 0);

    for (int l = 0; l < 3; l++) {
        int flip = (l == 1) ? 1 : 0;    // read set: l0->0, l1->1, l2->0
        // gathers on s2 (chunked), signal per chunk
        for (int c = 0; c < NCH; c++) {
            int node0 = tb[c] * 128;
            int ncnt = (tb[c + 1] * 128 < NN ? tb[c + 1] * 128 : NN) - node0;
            k_gather<<<(ncnt * 32 + 255) / 256, 256, 0, s2>>>(flip, node0, ncnt);
            cudaEventRecord(evG[l][c], s2);
        }
        // blocks on stream0, per-chunk dependency
        for (int c = 0; c < NCH; c++) {
            cudaStreamWaitEvent(0, evG[l][c], 0);
            k_block<<<tb[c + 1] - tb[c], NTHR, SM_BLK>>>(
                flip, tb[c], 1 + l, 4 + l, 7 + l, 10 + l, (l == 2), batch,
                sbl + l * FD, l1b + l * FD, l2b + l * FD,
                ln1g + l * FD, ln1b + l * FD, ln2g + l * FD, ln2b + l * FD);
        }
        if (l < 2) {
            cudaEventRecord(evLayer[l], 0);
            cudaStreamWaitEvent(s2, evLayer[l], 0);
        }
    }

    k_pool<<<NG / 8, 128, SM_POOL>>>(mdfW, mdfb, pg1, pb1, pW1, pb1l,
                                     pW2, pb2l, pg2, pb2, (float*)d_out);
}

// round 13
// speedup vs baseline: 1.0739x; 1.0739x over previous
#include <cuda_runtime.h>
#include <cuda_bf16.h>
#include <math.h>
#include <stdint.h>

#define NN 100000
#define NE 1600000
#define NG 1024
#define FD 128
#define NTILE 782           // ceil(NN/128)
#define NTHR 512

// ===================== scratch (device globals) =====================
__device__ float g_h[NN * FD];
__device__ float g_degf[NN];
__device__ int   g_deg[NN];
__device__ int   g_rowstart[NN + 1];
__device__ int   g_cursor[NN];
__device__ int   g_csrsrc[NE];
__device__ int   g_cnti[NG];
__device__ float g_cntf[NG];
__device__ float g_gm[NG * FD];
__device__ int   g_bsum[256];
// split activations in tile-swizzled layout (identical to smem layout -> flat cp.async)
__device__ __nv_bfloat16 g_agghi[NTILE * 16384];
__device__ __nv_bfloat16 g_agglo[NTILE * 16384];
__device__ __nv_bfloat16 g_hshi[NTILE * 16384];
__device__ __nv_bfloat16 g_hslo[NTILE * 16384];
// pre-transposed, split, swizzled weights: 13 matrices of 128x128 bf16
// m: 0=Win, 1..3=sage_Wl, 4..6=sage_Wr, 7..9=lin1, 10..12=lin2
__device__ __nv_bfloat16 g_whi[13 * 16384];
__device__ __nv_bfloat16 g_wlo[13 * 16384];

// ===================== helpers =====================
__device__ __forceinline__ uint32_t smem_u32(const void* p) {
    uint32_t a;
    asm("{ .reg .u64 t; cvta.to.shared.u64 t, %1; cvt.u32.u64 %0, t; }" : "=r"(a) : "l"(p));
    return a;
}

// XOR-swizzled byte offset inside a [128 rows][128 cols] bf16 tile (256B/row).
__device__ __forceinline__ uint32_t swoff(int row, int col) {
    return (uint32_t)row * 256u
         + ((uint32_t)(((col >> 3) ^ (row & 7)) & 15) << 4)
         + ((uint32_t)(col & 7) << 1);
}

#define LDM4(r0, r1, r2, r3, a) \
    asm volatile("ldmatrix.sync.aligned.m8n8.x4.shared.b16 {%0,%1,%2,%3}, [%4];" \
        : "=r"(r0), "=r"(r1), "=r"(r2), "=r"(r3) : "r"(a))

#define MMA16(c, a, b0, b1) \
    asm volatile("mma.sync.aligned.m16n8k16.row.col.f32.bf16.bf16.f32 " \
        "{%0,%1,%2,%3},{%4,%5,%6,%7},{%8,%9},{%0,%1,%2,%3};" \
        : "+f"((c)[0]), "+f"((c)[1]), "+f"((c)[2]), "+f"((c)[3]) \
        : "r"((a)[0]), "r"((a)[1]), "r"((a)[2]), "r"((a)[3]), "r"(b0), "r"(b1))

__device__ __forceinline__ void split4(float4 v, uint2& hi, uint2& lo) {
    __nv_bfloat16 hx = __float2bfloat16_rn(v.x), hy = __float2bfloat16_rn(v.y);
    __nv_bfloat16 hz = __float2bfloat16_rn(v.z), hw = __float2bfloat16_rn(v.w);
    float rx = v.x - __bfloat162float(hx), ry = v.y - __bfloat162float(hy);
    float rz = v.z - __bfloat162float(hz), rw = v.w - __bfloat162float(hw);
    __nv_bfloat162 H0; H0.x = hx; H0.y = hy;
    __nv_bfloat162 H1; H1.x = hz; H1.y = hw;
    __nv_bfloat162 L0 = __floats2bfloat162_rn(rx, ry);
    __nv_bfloat162 L1 = __floats2bfloat162_rn(rz, rw);
    hi.x = *(uint32_t*)&H0; hi.y = *(uint32_t*)&H1;
    lo.x = *(uint32_t*)&L0; lo.y = *(uint32_t*)&L1;
}

__device__ __forceinline__ float recon(const char* hi, const char* lo, uint32_t off,
                                       float& v1) {
    uint32_t uh = *(const uint32_t*)(hi + off);
    uint32_t ul = *(const uint32_t*)(lo + off);
    __nv_bfloat162 bh = *(__nv_bfloat162*)&uh;
    __nv_bfloat162 bl = *(__nv_bfloat162*)&ul;
    v1 = __bfloat162float(bh.y) + __bfloat162float(bl.y);
    return __bfloat162float(bh.x) + __bfloat162float(bl.x);
}

// fp32 global tile -> split bf16 swizzled smem (k_input only)
__device__ __forceinline__ void conv_tile(const float* __restrict__ src, int nbase,
                                          char* ahi, char* alo) {
#pragma unroll 2
    for (int i = threadIdx.x; i < 4096; i += NTHR) {
        int row = i >> 5, c4 = i & 31;
        int node = nbase + row;
        float4 v = make_float4(0.f, 0.f, 0.f, 0.f);
        if (node < NN) v = ((const float4*)src)[node * 32 + c4];
        uint2 h, l;
        split4(v, h, l);
        uint32_t off = swoff(row, c4 * 4);
        *(uint2*)(ahi + off) = h;
        *(uint2*)(alo + off) = l;
    }
}

// cp.async 32KB global -> smem (flat copy; layouts match)
__device__ __forceinline__ void copyw(const __nv_bfloat16* src, char* dst) {
    uint32_t d = smem_u32(dst);
    for (int i = threadIdx.x; i < 2048; i += NTHR)
        asm volatile("cp.async.cg.shared.global [%0], [%1], 16;"
                     :: "r"(d + i * 16), "l"(src + i * 8) : "memory");
}
#define CPCOMMIT() asm volatile("cp.async.commit_group;" ::: "memory")
#define CPWAITG(n) asm volatile("cp.async.wait_group %0;" :: "n"(n) : "memory")

// warp-tiled 3-term split GEMM: C[32x32] += (Ahi+Alo)@(Whi+Wlo) (dropping lo*lo)
__device__ __forceinline__ void gemm3(uint32_t ahi, uint32_t alo,
                                      uint32_t whi, uint32_t wlo,
                                      float C[2][4][4], int lane, int wR, int wC) {
    int arow = (lane & 7) + ((lane >> 3) & 1) * 8;
    int acolo = ((lane >> 4) & 1) * 8;
    int brow = (lane & 7) + ((lane >> 4) & 1) * 8;
    int bcolo = ((lane >> 3) & 1) * 8;
#pragma unroll
    for (int kk = 0; kk < 8; kk++) {
        int kbase = kk * 16;
        uint32_t ah[2][4], al[2][4];
#pragma unroll
        for (int mb = 0; mb < 2; mb++) {
            uint32_t oa = swoff(wR + mb * 16 + arow, kbase + acolo);
            LDM4(ah[mb][0], ah[mb][1], ah[mb][2], ah[mb][3], ahi + oa);
            LDM4(al[mb][0], al[mb][1], al[mb][2], al[mb][3], alo + oa);
        }
#pragma unroll
        for (int nbp = 0; nbp < 2; nbp++) {
            uint32_t ob = swoff(wC + nbp * 16 + brow, kbase + bcolo);
            uint32_t bh[4], bl[4];
            LDM4(bh[0], bh[1], bh[2], bh[3], whi + ob);
            LDM4(bl[0], bl[1], bl[2], bl[3], wlo + ob);
#pragma unroll
            for (int mb = 0; mb < 2; mb++) {
                MMA16(C[mb][2 * nbp],     ah[mb], bh[0], bh[1]);
                MMA16(C[mb][2 * nbp + 1], ah[mb], bh[2], bh[3]);
                MMA16(C[mb][2 * nbp],     ah[mb], bl[0], bl[1]);
                MMA16(C[mb][2 * nbp + 1], ah[mb], bl[2], bl[3]);
                MMA16(C[mb][2 * nbp],     al[mb], bh[0], bh[1]);
                MMA16(C[mb][2 * nbp + 1], al[mb], bh[2], bh[3]);
            }
        }
    }
}

#define ZEROC(C) do { \
    _Pragma("unroll") for (int _a = 0; _a < 2; _a++) \
    _Pragma("unroll") for (int _b = 0; _b < 4; _b++) \
    _Pragma("unroll") for (int _c = 0; _c < 4; _c++) (C)[_a][_b][_c] = 0.f; \
} while (0)

// stage C frags into fp32 smem [128][132]
__device__ __forceinline__ void stageC(float* stg, float C[2][4][4], int lane, int wR, int wC) {
    int r0 = wR + (lane >> 2);
    int c0 = wC + (lane & 3) * 2;
#pragma unroll
    for (int mb = 0; mb < 2; mb++) {
#pragma unroll
        for (int nb = 0; nb < 4; nb++) {
            int row = r0 + mb * 16;
            int col = c0 + nb * 8;
            *(float2*)(stg + row * 132 + col) = make_float2(C[mb][nb][0], C[mb][nb][1]);
            *(float2*)(stg + (row + 8) * 132 + col) = make_float2(C[mb][nb][2], C[mb][nb][3]);
        }
    }
}

// ===================== setup kernels =====================
__global__ void k_zero() {
    int i = blockIdx.x * blockDim.x + threadIdx.x;
    if (i < NN) g_deg[i] = 0;
    if (i < NG) g_cnti[i] = 0;
    if (i < NG * FD) g_gm[i] = 0.f;
}
__global__ void k_count(const int* __restrict__ ei, const int* __restrict__ batch) {
    int i = blockIdx.x * blockDim.x + threadIdx.x;
    if (i < NE) atomicAdd(&g_deg[ei[NE + i]], 1);
    if (i < NN) atomicAdd(&g_cnti[batch[i]], 1);
}
__global__ void k_scan1() {
    __shared__ int s[512];
    int i = blockIdx.x * 512 + threadIdx.x;
    int v = (i < NN) ? g_deg[i] : 0;
    s[threadIdx.x] = v;
    __syncthreads();
#pragma unroll
    for (int off = 1; off < 512; off <<= 1) {
        int t = (threadIdx.x >= off) ? s[threadIdx.x - off] : 0;
        __syncthreads();
        s[threadIdx.x] += t;
        __syncthreads();
    }
    if (i < NN) g_rowstart[i + 1] = s[threadIdx.x];
    if (threadIdx.x == 511) g_bsum[blockIdx.x] = s[511];
}
__global__ void k_scan23() {
    __shared__ int pre[256];
    const int nb = (NN + 511) / 512;  // 196
    int v = (threadIdx.x < nb) ? g_bsum[threadIdx.x] : 0;
    pre[threadIdx.x] = v;
    __syncthreads();
#pragma unroll
    for (int off = 1; off < 256; off <<= 1) {
        int t = (threadIdx.x >= off) ? pre[threadIdx.x - off] : 0;
        __syncthreads();
        pre[threadIdx.x] += t;
        __syncthreads();
    }
    pre[threadIdx.x] -= v;  // exclusive
    __syncthreads();
    int i = blockIdx.x * blockDim.x + threadIdx.x;
    if (i >= NN) return;
    int r = g_rowstart[i + 1] + pre[i >> 9];
    g_rowstart[i + 1] = r;
    g_cursor[i] = r - g_deg[i];
    g_degf[i] = fmaxf((float)g_deg[i], 1.f);
    if (i == 0) g_rowstart[0] = 0;
    if (i < NG) g_cntf[i] = fmaxf((float)g_cnti[i], 1.f);
}
__global__ void k_fill(const int* __restrict__ ei) {
    int e = blockIdx.x * blockDim.x + threadIdx.x;
    if (e >= NE) return;
    int src = ei[e];
    int dst = ei[NE + e];
    int pos = atomicAdd(&g_cursor[dst], 1);
    g_csrsrc[pos] = src;
}
// high-occupancy gather (fp32 h, float4 loads): written SPLIT+swizzled
__global__ void k_gather() {
    int gw = (blockIdx.x * blockDim.x + threadIdx.x) >> 5;
    int lane = threadIdx.x & 31;
    if (gw >= NN) return;
    int beg = g_rowstart[gw], end = g_rowstart[gw + 1];
    float4 acc = make_float4(0.f, 0.f, 0.f, 0.f);
    const float4* hv = (const float4*)g_h;
    int e = beg;
    for (; e + 4 <= end; e += 4) {
        int s0 = g_csrsrc[e], s1 = g_csrsrc[e + 1], s2 = g_csrsrc[e + 2], s3 = g_csrsrc[e + 3];
        float4 a0 = hv[s0 * 32 + lane];
        float4 a1 = hv[s1 * 32 + lane];
        float4 a2 = hv[s2 * 32 + lane];
        float4 a3 = hv[s3 * 32 + lane];
        acc.x += (a0.x + a1.x) + (a2.x + a3.x);
        acc.y += (a0.y + a1.y) + (a2.y + a3.y);
        acc.z += (a0.z + a1.z) + (a2.z + a3.z);
        acc.w += (a0.w + a1.w) + (a2.w + a3.w);
    }
    for (; e < end; ++e) {
        int s0 = g_csrsrc[e];
        float4 a0 = hv[s0 * 32 + lane];
        acc.x += a0.x; acc.y += a0.y; acc.z += a0.z; acc.w += a0.w;
    }
    float inv = 1.f / g_degf[gw];
    acc.x *= inv; acc.y *= inv; acc.z *= inv; acc.w *= inv;
    uint2 h, l;
    split4(acc, h, l);
    int tile = gw >> 7, row = gw & 127;
    uint32_t off = (uint32_t)tile * 32768u + swoff(row, lane * 4);
    *(uint2*)((char*)g_agghi + off) = h;
    *(uint2*)((char*)g_agglo + off) = l;
}
// weight prep: transpose to [N,K], split hi/lo bf16, swizzled (13 matrices)
__global__ void k_wprep(const float* __restrict__ Win, const float* __restrict__ sWl,
                        const float* __restrict__ sWr, const float* __restrict__ l1W,
                        const float* __restrict__ l2W) {
    int m = blockIdx.y;
    int idx = blockIdx.x * 256 + threadIdx.x;
    if (idx >= 16384) return;
    int n = idx >> 7, k = idx & 127;
    float v;
    if (m == 0)       v = Win[k * 128 + n];
    else if (m < 4)   v = sWl[(m - 1) * 16384 + k * 128 + n];
    else if (m < 7)   v = sWr[(m - 4) * 16384 + k * 128 + n];
    else if (m < 10)  v = l1W[(m - 7) * 16384 + k * 128 + n];
    else              v = l2W[(m - 10) * 16384 + k * 128 + n];
    __nv_bfloat16 hi = __float2bfloat16_rn(v);
    float r = v - __bfloat162float(hi);
    __nv_bfloat16 lo = __float2bfloat16_rn(r);
    uint32_t e = swoff(n, k) >> 1;
    g_whi[m * 16384 + e] = hi;
    g_wlo[m * 16384 + e] = lo;
}

// ===================== input GEMM: h = [x|w] @ W_in + b_in =====================
__global__ void __launch_bounds__(NTHR, 1) k_input(
    const float* __restrict__ x, const float* __restrict__ w,
    const float* __restrict__ Win, const float* __restrict__ bin) {
    extern __shared__ char dsm[];
    __shared__ float s_b[128], s_wr[128];
    uint32_t base = smem_u32(dsm);
    uint32_t ab = (base + 1023) & ~1023u;
    char* aptr = dsm + (ab - base);
    int tid = threadIdx.x;
    int lane = tid & 31, wid = tid >> 5;
    int wR = (wid >> 2) * 32, wC = (wid & 3) * 32;
    if (tid < 128) { s_b[tid] = bin[tid]; s_wr[tid] = Win[128 * 128 + tid]; }
    copyw(g_whi, aptr + 65536);
    copyw(g_wlo, aptr + 98304);
    CPCOMMIT();
    int tile = blockIdx.x;
    int nbase = tile * 128;
    conv_tile(x, nbase, aptr, aptr + 32768);
    CPWAITG(0);
    __syncthreads();
    float C[2][4][4];
    ZEROC(C);
    gemm3(ab, ab + 32768, ab + 65536, ab + 98304, C, lane, wR, wC);
    __syncthreads();
    float* stg = (float*)aptr;
    stageC(stg, C, lane, wR, wC);
    __syncthreads();
#pragma unroll 2
    for (int i = tid; i < 4096; i += NTHR) {
        int row = i >> 5, c4 = i & 31;
        int nd = nbase + row;
        if (nd < NN) {
            float wn = w[nd];
            float4 v = ((float4*)(stg + row * 132))[c4];
            float4 o;
            o.x = v.x + s_b[c4 * 4 + 0] + wn * s_wr[c4 * 4 + 0];
            o.y = v.y + s_b[c4 * 4 + 1] + wn * s_wr[c4 * 4 + 1];
            o.z = v.z + s_b[c4 * 4 + 2] + wn * s_wr[c4 * 4 + 2];
            o.w = v.w + s_b[c4 * 4 + 3] + wn * s_wr[c4 * 4 + 3];
            ((float4*)g_h)[nd * 32 + c4] = o;
            uint2 h, l;
            split4(o, h, l);
            uint32_t off = (uint32_t)tile * 32768u + swoff(row, c4 * 4);
            *(uint2*)((char*)g_hshi + off) = h;
            *(uint2*)((char*)g_hslo + off) = l;
        }
    }
}

// ===================== fused sage+FFN block (buffer-rotated pipeline) ==========
__global__ void __launch_bounds__(NTHR, 1) k_block(
    int wlm, int wrm, int w1m, int w2m, int last,
    const int* __restrict__ batch,
    const float* __restrict__ bl, const float* __restrict__ b1,
    const float* __restrict__ b2,
    const float* __restrict__ g1, const float* __restrict__ e1,
    const float* __restrict__ g2, const float* __restrict__ e2) {
    extern __shared__ char dsm[];
    __shared__ float s_bl[128], s_b1[128], s_b2[128];
    __shared__ float s_g1[128], s_e1[128], s_g2[128], s_e2[128];
    __shared__ float red_s[4][128], red_q[4][128];
    __shared__ int s_batch[128];
    uint32_t base = smem_u32(dsm);
    uint32_t ab = (base + 1023) & ~1023u;
    char* aptr = dsm + (ab - base);
    char* p_ahi = aptr;
    char* p_alo = aptr + 32768;
    char* p_whi = aptr + 65536;
    char* p_wlo = aptr + 98304;
    char* p_yhi = aptr + 131072;
    char* p_ylo = aptr + 163840;
    int tid = threadIdx.x, lane = tid & 31, wid = tid >> 5;
    int wR = (wid >> 2) * 32, wC = (wid & 3) * 32;
    int cg = wid & 3;
    int r0 = wR + (lane >> 2);
    int c0l = (lane & 3) * 2;
    int tile = blockIdx.x;
    int nbase = tile * 128;

    copyw(g_agghi + tile * 16384, p_ahi);
    copyw(g_agglo + tile * 16384, p_alo);
    copyw(g_whi + wlm * 16384, p_whi);
    copyw(g_wlo + wlm * 16384, p_wlo);
    CPCOMMIT();
    copyw(g_hshi + tile * 16384, p_yhi);
    copyw(g_hslo + tile * 16384, p_ylo);
    CPCOMMIT();
    if (tid < 128) {
        s_bl[tid] = bl[tid]; s_b1[tid] = b1[tid]; s_b2[tid] = b2[tid];
        s_g1[tid] = g1[tid]; s_e1[tid] = e1[tid];
        s_g2[tid] = g2[tid]; s_e2[tid] = e2[tid];
        if (last) {
            int nd = nbase + tid;
            s_batch[tid] = (nd < NN) ? batch[nd] : -1;
        }
    }
    CPWAITG(1);   // agg + Wl ready
    __syncthreads();

    // ---- sage GEMM 1: agg @ Wl ----
    float C[2][4][4];
    ZEROC(C);
    gemm3(ab, ab + 32768, ab + 65536, ab + 98304, C, lane, wR, wC);
    __syncthreads();

    // ---- sage GEMM 2: h(Y) @ Wr ----
    copyw(g_whi + wrm * 16384, p_whi);
    copyw(g_wlo + wrm * 16384, p_wlo);
    CPCOMMIT();
    CPWAITG(0);
    __syncthreads();
    gemm3(ab + 131072, ab + 163840, ab + 65536, ab + 98304, C, lane, wR, wC);
    __syncthreads();

    // prefetch W1 under LN1
    copyw(g_whi + w1m * 16384, p_whi);
    copyw(g_wlo + w1m * 16384, p_wlo);
    CPCOMMIT();

    // ---- LN1 (+ h residual from Y split) ----
    {
        float sp[4], qp[4];
#pragma unroll
        for (int mb = 0; mb < 2; mb++)
#pragma unroll
            for (int h = 0; h < 2; h++) {
                int R = r0 + mb * 16 + h * 8;
                float s = 0.f, q = 0.f;
#pragma unroll
                for (int nb = 0; nb < 4; nb++) {
                    int col = wC + c0l + nb * 8;
                    float h1;
                    float h0 = recon(p_yhi, p_ylo, swoff(R, col), h1);
                    float v0 = C[mb][nb][2 * h + 0] + s_bl[col] + h0;
                    float v1 = C[mb][nb][2 * h + 1] + s_bl[col + 1] + h1;
                    C[mb][nb][2 * h + 0] = v0;
                    C[mb][nb][2 * h + 1] = v1;
                    s += v0 + v1;
                    q += v0 * v0 + v1 * v1;
                }
                sp[mb * 2 + h] = s; qp[mb * 2 + h] = q;
            }
#pragma unroll
        for (int k = 0; k < 4; k++) {
            sp[k] += __shfl_xor_sync(0xffffffffu, sp[k], 1);
            sp[k] += __shfl_xor_sync(0xffffffffu, sp[k], 2);
            qp[k] += __shfl_xor_sync(0xffffffffu, qp[k], 1);
            qp[k] += __shfl_xor_sync(0xffffffffu, qp[k], 2);
        }
        if ((lane & 3) == 0) {
#pragma unroll
            for (int k = 0; k < 4; k++) {
                int R = r0 + (k >> 1) * 16 + (k & 1) * 8;
                red_s[cg][R] = sp[k];
                red_q[cg][R] = qp[k];
            }
        }
    }
    __syncthreads();
    // normalize -> y1, write split into A (agg dead)
#pragma unroll
    for (int mb = 0; mb < 2; mb++)
#pragma unroll
        for (int h = 0; h < 2; h++) {
            int R = r0 + mb * 16 + h * 8;
            float S = red_s[0][R] + red_s[1][R] + red_s[2][R] + red_s[3][R];
            float Q = red_q[0][R] + red_q[1][R] + red_q[2][R] + red_q[3][R];
            float mu = S * 0.0078125f;
            float var = Q * 0.0078125f - mu * mu;
            float inv = rsqrtf(var + 1e-5f);
#pragma unroll
            for (int nb = 0; nb < 4; nb++) {
                int col = wC + c0l + nb * 8;
                float y0 = (C[mb][nb][2 * h + 0] - mu) * inv * s_g1[col] + s_e1[col];
                float y1v = (C[mb][nb][2 * h + 1] - mu) * inv * s_g1[col + 1] + s_e1[col + 1];
                __nv_bfloat16 h0 = __float2bfloat16_rn(y0);
                __nv_bfloat16 h1 = __float2bfloat16_rn(y1v);
                __nv_bfloat162 HP; HP.x = h0; HP.y = h1;
                __nv_bfloat162 LP = __floats2bfloat162_rn(y0 - __bfloat162float(h0),
                                                          y1v - __bfloat162float(h1));
                uint32_t off = swoff(R, col);
                *(uint32_t*)(p_ahi + off) = *(uint32_t*)&HP;
                *(uint32_t*)(p_alo + off) = *(uint32_t*)&LP;
            }
        }
    CPWAITG(0);
    __syncthreads();

    // ---- FFN GEMM 1: y1(A) @ W1 ----
    ZEROC(C);
    gemm3(ab, ab + 32768, ab + 65536, ab + 98304, C, lane, wR, wC);
    __syncthreads();

    copyw(g_whi + w2m * 16384, p_whi);
    copyw(g_wlo + w2m * 16384, p_wlo);
    CPCOMMIT();

    // elu(C + b1) -> split into Y (h dead)
#pragma unroll
    for (int mb = 0; mb < 2; mb++)
#pragma unroll
        for (int nb = 0; nb < 4; nb++) {
            int col = wC + c0l + nb * 8;
#pragma unroll
            for (int h = 0; h < 2; h++) {
                int R = r0 + mb * 16 + h * 8;
                float t0 = C[mb][nb][2 * h + 0] + s_b1[col];
                float t1 = C[mb][nb][2 * h + 1] + s_b1[col + 1];
                t0 = t0 > 0.f ? t0 : expm1f(t0);
                t1 = t1 > 0.f ? t1 : expm1f(t1);
                __nv_bfloat16 h0 = __float2bfloat16_rn(t0);
                __nv_bfloat16 h1 = __float2bfloat16_rn(t1);
                __nv_bfloat162 HP; HP.x = h0; HP.y = h1;
                __nv_bfloat162 LP = __floats2bfloat162_rn(t0 - __bfloat162float(h0),
                                                          t1 - __bfloat162float(h1));
                uint32_t off = swoff(R, col);
                *(uint32_t*)(p_yhi + off) = *(uint32_t*)&HP;
                *(uint32_t*)(p_ylo + off) = *(uint32_t*)&LP;
            }
        }
    CPWAITG(0);
    __syncthreads();

    // ---- FFN GEMM 2: elu(Y) @ W2 ----
    ZEROC(C);
    gemm3(ab + 131072, ab + 163840, ab + 65536, ab + 98304, C, lane, wR, wC);

    // ---- LN2 (+ y1 residual from A split) ----
    {
        float sp[4], qp[4];
#pragma unroll
        for (int mb = 0; mb < 2; mb++)
#pragma unroll
            for (int h = 0; h < 2; h++) {
                int R = r0 + mb * 16 + h * 8;
                float s = 0.f, q = 0.f;
#pragma unroll
                for (int nb = 0; nb < 4; nb++) {
                    int col = wC + c0l + nb * 8;
                    float y1v;
                    float y0 = recon(p_ahi, p_alo, swoff(R, col), y1v);
                    float v0 = C[mb][nb][2 * h + 0] + s_b2[col] + y0;
                    float v1 = C[mb][nb][2 * h + 1] + s_b2[col + 1] + y1v;
                    C[mb][nb][2 * h + 0] = v0;
                    C[mb][nb][2 * h + 1] = v1;
                    s += v0 + v1;
                    q += v0 * v0 + v1 * v1;
                }
                sp[mb * 2 + h] = s; qp[mb * 2 + h] = q;
            }
#pragma unroll
        for (int k = 0; k < 4; k++) {
            sp[k] += __shfl_xor_sync(0xffffffffu, sp[k], 1);
            sp[k] += __shfl_xor_sync(0xffffffffu, sp[k], 2);
            qp[k] += __shfl_xor_sync(0xffffffffu, qp[k], 1);
            qp[k] += __shfl_xor_sync(0xffffffffu, qp[k], 2);
        }
        if ((lane & 3) == 0) {
#pragma unroll
            for (int k = 0; k < 4; k++) {
                int R = r0 + (k >> 1) * 16 + (k & 1) * 8;
                red_s[cg][R] = sp[k];
                red_q[cg][R] = qp[k];
            }
        }
    }
    __syncthreads();
    float* stg = (float*)(aptr + 65536);
#pragma unroll
    for (int mb = 0; mb < 2; mb++)
#pragma unroll
        for (int h = 0; h < 2; h++) {
            int R = r0 + mb * 16 + h * 8;
            float S = red_s[0][R] + red_s[1][R] + red_s[2][R] + red_s[3][R];
            float Q = red_q[0][R] + red_q[1][R] + red_q[2][R] + red_q[3][R];
            float mu = S * 0.0078125f;
            float var = Q * 0.0078125f - mu * mu;
            float inv = rsqrtf(var + 1e-5f);
#pragma unroll
            for (int nb = 0; nb < 4; nb++) {
                int col = wC + c0l + nb * 8;
                float o0 = (C[mb][nb][2 * h + 0] - mu) * inv * s_g2[col] + s_e2[col];
                float o1 = (C[mb][nb][2 * h + 1] - mu) * inv * s_g2[col + 1] + s_e2[col + 1];
                *(float2*)(stg + R * 132 + col) = make_float2(o0, o1);
            }
        }
    __syncthreads();
    if (!last) {
#pragma unroll 2
        for (int i = tid; i < 4096; i += NTHR) {
            int row = i >> 5, c4 = i & 31;
            int nd = nbase + row;
            if (nd < NN) {
                float4 v = ((float4*)(stg + row * 132))[c4];
                ((float4*)g_h)[nd * 32 + c4] = v;
                uint2 h, l;
                split4(v, h, l);
                uint32_t off = (uint32_t)tile * 32768u + swoff(row, c4 * 4);
                *(uint2*)((char*)g_hshi + off) = h;
                *(uint2*)((char*)g_hslo + off) = l;
            }
        }
    } else {
        int f = tid & 127, q = tid >> 7;
        int rbeg = q * 32;
        int cur = s_batch[rbeg];
        float acc = 0.f;
#pragma unroll 4
        for (int r = rbeg; r < rbeg + 32; r++) {
            int bg = s_batch[r];
            if (bg < 0) break;
            if (bg != cur) {
                atomicAdd(&g_gm[cur * FD + f], acc);
                acc = 0.f;
                cur = bg;
            }
            acc += stg[r * 132 + f];
        }
        if (cur >= 0) atomicAdd(&g_gm[cur * FD + f], acc);
    }
}

// ===================== head =====================
__global__ void __launch_bounds__(128, 1) k_pool(
    const float* __restrict__ mdfW, const float* __restrict__ mdfb,
    const float* __restrict__ pg1, const float* __restrict__ pb1,
    const float* __restrict__ W1, const float* __restrict__ b1,
    const float* __restrict__ W2, const float* __restrict__ b2,
    const float* __restrict__ pg2, const float* __restrict__ pb2,
    float* __restrict__ out) {
    extern __shared__ float ws[];
    __shared__ float vm[128], hh[128], tt[128], red[8];
    int f = threadIdx.x, lane = f & 31, wp = f >> 5;
    for (int i = f; i < 16384; i += 128) {
        ws[i] = mdfW[i];
        ws[16384 + i] = W1[i];
        ws[32768 + i] = W2[i];
    }
    float c_mb = mdfb[f], c_g1 = pg1[f], c_b1 = pb1[f];
    float c_bl1 = b1[f], c_bl2 = b2[f], c_g2 = pg2[f], c_b2 = pb2[f];
    __syncthreads();
    for (int gi = 0; gi < 8; gi++) {
        int g = blockIdx.x * 8 + gi;
        vm[f] = g_gm[g * FD + f] / g_cntf[g];
        __syncthreads();
        float p = 0.f;
#pragma unroll 4
        for (int k = 0; k < 128; k++) p = fmaf(vm[k], ws[k * 128 + f], p);
        p += c_mb;
        float s = p, q = p * p;
#pragma unroll
        for (int off = 16; off; off >>= 1) {
            s += __shfl_xor_sync(0xffffffffu, s, off);
            q += __shfl_xor_sync(0xffffffffu, q, off);
        }
        if (lane == 0) { red[wp] = s; red[4 + wp] = q; }
        __syncthreads();
        s = red[0] + red[1] + red[2] + red[3];
        q = red[4] + red[5] + red[6] + red[7];
        float mu = s * 0.0078125f;
        float var = q * 0.0078125f - mu * mu;
        float inv = rsqrtf(var + 1e-5f);
        float h0 = (p - mu) * inv * c_g1 + c_b1;
        __syncthreads();
        hh[f] = h0;
        __syncthreads();
        float a = 0.f;
#pragma unroll 4
        for (int k = 0; k < 128; k++) a = fmaf(hh[k], ws[16384 + k * 128 + f], a);
        a += c_bl1;
        a = a > 0.f ? a : expm1f(a);
        tt[f] = a;
        __syncthreads();
        float y = 0.f;
#pragma unroll 4
        for (int k = 0; k < 128; k++) y = fmaf(tt[k], ws[32768 + k * 128 + f], y);
        y += c_bl2;
        float v2 = y + h0;
        s = v2; q = v2 * v2;
#pragma unroll
        for (int off = 16; off; off >>= 1) {
            s += __shfl_xor_sync(0xffffffffu, s, off);
            q += __shfl_xor_sync(0xffffffffu, q, off);
        }
        if (lane == 0) { red[wp] = s; red[4 + wp] = q; }
        __syncthreads();
        s = red[0] + red[1] + red[2] + red[3];
        q = red[4] + red[5] + red[6] + red[7];
        mu = s * 0.0078125f;
        var = q * 0.0078125f - mu * mu;
        inv = rsqrtf(var + 1e-5f);
        out[g * FD + f] = (v2 - mu) * inv * c_g2 + c_b2;
        __syncthreads();
    }
}

// ===================== launcher (setup-phase fork only) =====================
extern "C" void kernel_launch(void* const* d_in, const int* in_sizes, int n_in,
                              void* d_out, int out_size) {
    const float* x    = (const float*)d_in[0];
    const float* w    = (const float*)d_in[1];
    const int*   ei   = (const int*)d_in[2];
    const int*   batch= (const int*)d_in[3];
    const float* Win  = (const float*)d_in[4];
    const float* bin  = (const float*)d_in[5];
    const float* sWl  = (const float*)d_in[6];
    const float* sbl  = (const float*)d_in[7];
    const float* sWr  = (const float*)d_in[8];
    const float* ln1g = (const float*)d_in[9];
    const float* ln1b = (const float*)d_in[10];
    const float* l1W  = (const float*)d_in[11];
    const float* l1b  = (const float*)d_in[12];
    const float* l2W  = (const float*)d_in[13];
    const float* l2b  = (const float*)d_in[14];
    const float* ln2g = (const float*)d_in[15];
    const float* ln2b = (const float*)d_in[16];
    const float* mdfW = (const float*)d_in[17];
    const float* mdfb = (const float*)d_in[18];
    const float* pg1  = (const float*)d_in[19];
    const float* pb1  = (const float*)d_in[20];
    const float* pW1  = (const float*)d_in[21];
    const float* pb1l = (const float*)d_in[22];
    const float* pW2  = (const float*)d_in[23];
    const float* pb2l = (const float*)d_in[24];
    const float* pg2  = (const float*)d_in[25];
    const float* pb2  = (const float*)d_in[26];

    const int SM_BLK = 1024 + 196608;
    const int SM_SML = 1024 + 131072;
    const int SM_POOL = 49152 * 4;
    cudaFuncSetAttribute(k_input, cudaFuncAttributeMaxDynamicSharedMemorySize, SM_SML);
    cudaFuncSetAttribute(k_block, cudaFuncAttributeMaxDynamicSharedMemorySize, SM_BLK);
    cudaFuncSetAttribute(k_pool,  cudaFuncAttributeMaxDynamicSharedMemorySize, SM_POOL);

    cudaStream_t s2;
    cudaStreamCreateWithFlags(&s2, cudaStreamNonBlocking);
    cudaEvent_t evFork, evCSR;
    cudaEventCreateWithFlags(&evFork, cudaEventDisableTiming);
    cudaEventCreateWithFlags(&evCSR, cudaEventDisableTiming);

    // fork: CSR build on s2, weights + input GEMM on stream0
    k_zero<<<512, 256>>>();
    cudaEventRecord(evFork, 0);
    cudaStreamWaitEvent(s2, evFork, 0);

    k_count<<<(NE + 255) / 256, 256, 0, s2>>>(ei, batch);
    k_scan1<<<(NN + 511) / 512, 512, 0, s2>>>();
    k_scan23<<<(NN + 255) / 256, 256, 0, s2>>>();
    k_fill<<<(NE + 255) / 256, 256, 0, s2>>>(ei);
    cudaEventRecord(evCSR, s2);

    k_wprep<<<dim3(64, 13), 256>>>(Win, sWl, sWr, l1W, l2W);
    k_input<<<NTILE, NTHR, SM_SML>>>(x, w, Win, bin);
    cudaStreamWaitEvent(0, evCSR, 0);   // join before first gather

    for (int l = 0; l < 3; l++) {
        k_gather<<<(NN * 32 + 255) / 256, 256>>>();
        k_block<<<NTILE, NTHR, SM_BLK>>>(1 + l, 4 + l, 7 + l, 10 + l, (l == 2),
                                         batch,
                                         sbl + l * FD, l1b + l * FD, l2b + l * FD,
                                         ln1g + l * FD, ln1b + l * FD,
                                         ln2g + l * FD, ln2b + l * FD);
    }

    k_pool<<<NG / 8, 128, SM_POOL>>>(mdfW, mdfb, pg1, pb1, pW1, pb1l,
                                     pW2, pb2l, pg2, pb2, (float*)d_out);
}

// round 14
// speedup vs baseline: 1.2480x; 1.1621x over previous
#include <cuda_runtime.h>
#include <cuda_bf16.h>
#include <math.h>
#include <stdint.h>

#define NN 100000
#define NE 1600000
#define NG 1024
#define FD 128
#define TR 64               // tile rows
#define NT2 1563            // ceil(NN/64)
#define NTHR 256

// ===================== scratch (device globals) =====================
__device__ float g_h[NN * FD];
__device__ float g_degf[NN];
__device__ int   g_deg[NN];
__device__ int   g_rowstart[NN + 1];
__device__ int   g_cursor[NN];
__device__ int   g_csrsrc[NE];
__device__ int   g_cnti[NG];
__device__ float g_cntf[NG];
__device__ float g_gm[NG * FD];
__device__ int   g_bsum[256];
// split activations in 64-row tile-swizzled layout (16KB per tile per component)
__device__ __nv_bfloat16 g_agghi[NT2 * 8192];
__device__ __nv_bfloat16 g_agglo[NT2 * 8192];
__device__ __nv_bfloat16 g_hshi[NT2 * 8192];
__device__ __nv_bfloat16 g_hslo[NT2 * 8192];
// pre-transposed, split, swizzled weights: 13 matrices of 128x128 bf16
// m: 0=Win, 1..3=sage_Wl, 4..6=sage_Wr, 7..9=lin1, 10..12=lin2
__device__ __nv_bfloat16 g_whi[13 * 16384];
__device__ __nv_bfloat16 g_wlo[13 * 16384];

// ===================== helpers =====================
__device__ __forceinline__ uint32_t smem_u32(const void* p) {
    uint32_t a;
    asm("{ .reg .u64 t; cvta.to.shared.u64 t, %1; cvt.u32.u64 %0, t; }" : "=r"(a) : "l"(p));
    return a;
}

// XOR-swizzled byte offset inside a [rows][128 cols] bf16 tile (256B/row).
__device__ __forceinline__ uint32_t swoff(int row, int col) {
    return (uint32_t)row * 256u
         + ((uint32_t)(((col >> 3) ^ (row & 7)) & 15) << 4)
         + ((uint32_t)(col & 7) << 1);
}

#define LDM4(r0, r1, r2, r3, a) \
    asm volatile("ldmatrix.sync.aligned.m8n8.x4.shared.b16 {%0,%1,%2,%3}, [%4];" \
        : "=r"(r0), "=r"(r1), "=r"(r2), "=r"(r3) : "r"(a))

#define MMA16(c, a, b0, b1) \
    asm volatile("mma.sync.aligned.m16n8k16.row.col.f32.bf16.bf16.f32 " \
        "{%0,%1,%2,%3},{%4,%5,%6,%7},{%8,%9},{%0,%1,%2,%3};" \
        : "+f"((c)[0]), "+f"((c)[1]), "+f"((c)[2]), "+f"((c)[3]) \
        : "r"((a)[0]), "r"((a)[1]), "r"((a)[2]), "r"((a)[3]), "r"(b0), "r"(b1))

__device__ __forceinline__ void split4(float4 v, uint2& hi, uint2& lo) {
    __nv_bfloat16 hx = __float2bfloat16_rn(v.x), hy = __float2bfloat16_rn(v.y);
    __nv_bfloat16 hz = __float2bfloat16_rn(v.z), hw = __float2bfloat16_rn(v.w);
    float rx = v.x - __bfloat162float(hx), ry = v.y - __bfloat162float(hy);
    float rz = v.z - __bfloat162float(hz), rw = v.w - __bfloat162float(hw);
    __nv_bfloat162 H0; H0.x = hx; H0.y = hy;
    __nv_bfloat162 H1; H1.x = hz; H1.y = hw;
    __nv_bfloat162 L0 = __floats2bfloat162_rn(rx, ry);
    __nv_bfloat162 L1 = __floats2bfloat162_rn(rz, rw);
    hi.x = *(uint32_t*)&H0; hi.y = *(uint32_t*)&H1;
    lo.x = *(uint32_t*)&L0; lo.y = *(uint32_t*)&L1;
}

__device__ __forceinline__ float recon(const char* hi, const char* lo, uint32_t off,
                                       float& v1) {
    uint32_t uh = *(const uint32_t*)(hi + off);
    uint32_t ul = *(const uint32_t*)(lo + off);
    __nv_bfloat162 bh = *(__nv_bfloat162*)&uh;
    __nv_bfloat162 bl = *(__nv_bfloat162*)&ul;
    v1 = __bfloat162float(bh.y) + __bfloat162float(bl.y);
    return __bfloat162float(bh.x) + __bfloat162float(bl.x);
}

// fp32 global 64-row tile -> split bf16 swizzled smem (k_input only)
__device__ __forceinline__ void conv_tile(const float* __restrict__ src, int nbase,
                                          char* ahi, char* alo) {
#pragma unroll 2
    for (int i = threadIdx.x; i < 2048; i += NTHR) {
        int row = i >> 5, c4 = i & 31;
        int node = nbase + row;
        float4 v = make_float4(0.f, 0.f, 0.f, 0.f);
        if (node < NN) v = ((const float4*)src)[node * 32 + c4];
        uint2 h, l;
        split4(v, h, l);
        uint32_t off = swoff(row, c4 * 4);
        *(uint2*)(ahi + off) = h;
        *(uint2*)(alo + off) = l;
    }
}

// cp.async nbytes global -> smem (flat copy; layouts match)
__device__ __forceinline__ void copyg(const __nv_bfloat16* src, char* dst, int n16) {
    uint32_t d = smem_u32(dst);
    for (int i = threadIdx.x; i < n16; i += NTHR)
        asm volatile("cp.async.cg.shared.global [%0], [%1], 16;"
                     :: "r"(d + i * 16), "l"(src + i * 8) : "memory");
}
#define CPCOMMIT() asm volatile("cp.async.commit_group;" ::: "memory")
#define CPWAITG(n) asm volatile("cp.async.wait_group %0;" :: "n"(n) : "memory")

// warp-tiled 3-term split GEMM: C[32x32] += (Ahi+Alo)@(Whi+Wlo) (dropping lo*lo)
// A tile has 64 rows (wR in {0,32}); W tile has 128 rows.
__device__ __forceinline__ void gemm3(uint32_t ahi, uint32_t alo,
                                      uint32_t whi, uint32_t wlo,
                                      float C[2][4][4], int lane, int wR, int wC) {
    int arow = (lane & 7) + ((lane >> 3) & 1) * 8;
    int acolo = ((lane >> 4) & 1) * 8;
    int brow = (lane & 7) + ((lane >> 4) & 1) * 8;
    int bcolo = ((lane >> 3) & 1) * 8;
#pragma unroll
    for (int kk = 0; kk < 8; kk++) {
        int kbase = kk * 16;
        uint32_t ah[2][4], al[2][4];
#pragma unroll
        for (int mb = 0; mb < 2; mb++) {
            uint32_t oa = swoff(wR + mb * 16 + arow, kbase + acolo);
            LDM4(ah[mb][0], ah[mb][1], ah[mb][2], ah[mb][3], ahi + oa);
            LDM4(al[mb][0], al[mb][1], al[mb][2], al[mb][3], alo + oa);
        }
#pragma unroll
        for (int nbp = 0; nbp < 2; nbp++) {
            uint32_t ob = swoff(wC + nbp * 16 + brow, kbase + bcolo);
            uint32_t bh[4], bl[4];
            LDM4(bh[0], bh[1], bh[2], bh[3], whi + ob);
            LDM4(bl[0], bl[1], bl[2], bl[3], wlo + ob);
#pragma unroll
            for (int mb = 0; mb < 2; mb++) {
                MMA16(C[mb][2 * nbp],     ah[mb], bh[0], bh[1]);
                MMA16(C[mb][2 * nbp + 1], ah[mb], bh[2], bh[3]);
                MMA16(C[mb][2 * nbp],     ah[mb], bl[0], bl[1]);
                MMA16(C[mb][2 * nbp + 1], ah[mb], bl[2], bl[3]);
                MMA16(C[mb][2 * nbp],     al[mb], bh[0], bh[1]);
                MMA16(C[mb][2 * nbp + 1], al[mb], bh[2], bh[3]);
            }
        }
    }
}

#define ZEROC(C) do { \
    _Pragma("unroll") for (int _a = 0; _a < 2; _a++) \
    _Pragma("unroll") for (int _b = 0; _b < 4; _b++) \
    _Pragma("unroll") for (int _c = 0; _c < 4; _c++) (C)[_a][_b][_c] = 0.f; \
} while (0)

// stage C frags into fp32 smem [64][132]
__device__ __forceinline__ void stageC(float* stg, float C[2][4][4], int lane, int wR, int wC) {
    int r0 = wR + (lane >> 2);
    int c0 = wC + (lane & 3) * 2;
#pragma unroll
    for (int mb = 0; mb < 2; mb++) {
#pragma unroll
        for (int nb = 0; nb < 4; nb++) {
            int row = r0 + mb * 16;
            int col = c0 + nb * 8;
            *(float2*)(stg + row * 132 + col) = make_float2(C[mb][nb][0], C[mb][nb][1]);
            *(float2*)(stg + (row + 8) * 132 + col) = make_float2(C[mb][nb][2], C[mb][nb][3]);
        }
    }
}

// ===================== setup kernels =====================
__global__ void k_zero() {
    int i = blockIdx.x * blockDim.x + threadIdx.x;
    if (i < NN) g_deg[i] = 0;
    if (i < NG) g_cnti[i] = 0;
    if (i < NG * FD) g_gm[i] = 0.f;
}
__global__ void k_count(const int* __restrict__ ei, const int* __restrict__ batch) {
    int i = blockIdx.x * blockDim.x + threadIdx.x;
    if (i < NE) atomicAdd(&g_deg[ei[NE + i]], 1);
    if (i < NN) atomicAdd(&g_cnti[batch[i]], 1);
}
__global__ void k_scan1() {
    __shared__ int s[512];
    int i = blockIdx.x * 512 + threadIdx.x;
    int v = (i < NN) ? g_deg[i] : 0;
    s[threadIdx.x] = v;
    __syncthreads();
#pragma unroll
    for (int off = 1; off < 512; off <<= 1) {
        int t = (threadIdx.x >= off) ? s[threadIdx.x - off] : 0;
        __syncthreads();
        s[threadIdx.x] += t;
        __syncthreads();
    }
    if (i < NN) g_rowstart[i + 1] = s[threadIdx.x];
    if (threadIdx.x == 511) g_bsum[blockIdx.x] = s[511];
}
__global__ void k_scan23() {
    __shared__ int pre[256];
    const int nb = (NN + 511) / 512;  // 196
    int v = (threadIdx.x < nb) ? g_bsum[threadIdx.x] : 0;
    pre[threadIdx.x] = v;
    __syncthreads();
#pragma unroll
    for (int off = 1; off < 256; off <<= 1) {
        int t = (threadIdx.x >= off) ? pre[threadIdx.x - off] : 0;
        __syncthreads();
        pre[threadIdx.x] += t;
        __syncthreads();
    }
    pre[threadIdx.x] -= v;  // exclusive
    __syncthreads();
    int i = blockIdx.x * blockDim.x + threadIdx.x;
    if (i >= NN) return;
    int r = g_rowstart[i + 1] + pre[i >> 9];
    g_rowstart[i + 1] = r;
    g_cursor[i] = r - g_deg[i];
    g_degf[i] = fmaxf((float)g_deg[i], 1.f);
    if (i == 0) g_rowstart[0] = 0;
    if (i < NG) g_cntf[i] = fmaxf((float)g_cnti[i], 1.f);
}
__global__ void k_fill(const int* __restrict__ ei) {
    int e = blockIdx.x * blockDim.x + threadIdx.x;
    if (e >= NE) return;
    int src = ei[e];
    int dst = ei[NE + e];
    int pos = atomicAdd(&g_cursor[dst], 1);
    g_csrsrc[pos] = src;
}
// high-occupancy gather (fp32 h, float4 loads): written SPLIT+swizzled (64-row tiles)
__global__ void k_gather() {
    int gw = (blockIdx.x * blockDim.x + threadIdx.x) >> 5;
    int lane = threadIdx.x & 31;
    if (gw >= NN) return;
    int beg = g_rowstart[gw], end = g_rowstart[gw + 1];
    float4 acc = make_float4(0.f, 0.f, 0.f, 0.f);
    const float4* hv = (const float4*)g_h;
    int e = beg;
    for (; e + 4 <= end; e += 4) {
        int s0 = g_csrsrc[e], s1 = g_csrsrc[e + 1], s2 = g_csrsrc[e + 2], s3 = g_csrsrc[e + 3];
        float4 a0 = hv[s0 * 32 + lane];
        float4 a1 = hv[s1 * 32 + lane];
        float4 a2 = hv[s2 * 32 + lane];
        float4 a3 = hv[s3 * 32 + lane];
        acc.x += (a0.x + a1.x) + (a2.x + a3.x);
        acc.y += (a0.y + a1.y) + (a2.y + a3.y);
        acc.z += (a0.z + a1.z) + (a2.z + a3.z);
        acc.w += (a0.w + a1.w) + (a2.w + a3.w);
    }
    for (; e < end; ++e) {
        int s0 = g_csrsrc[e];
        float4 a0 = hv[s0 * 32 + lane];
        acc.x += a0.x; acc.y += a0.y; acc.z += a0.z; acc.w += a0.w;
    }
    float inv = 1.f / g_degf[gw];
    acc.x *= inv; acc.y *= inv; acc.z *= inv; acc.w *= inv;
    uint2 h, l;
    split4(acc, h, l);
    int tile = gw >> 6, row = gw & 63;
    uint32_t off = (uint32_t)tile * 16384u + swoff(row, lane * 4);
    *(uint2*)((char*)g_agghi + off) = h;
    *(uint2*)((char*)g_agglo + off) = l;
}
// weight prep: transpose to [N,K], split hi/lo bf16, swizzled (13 matrices)
__global__ void k_wprep(const float* __restrict__ Win, const float* __restrict__ sWl,
                        const float* __restrict__ sWr, const float* __restrict__ l1W,
                        const float* __restrict__ l2W) {
    int m = blockIdx.y;
    int idx = blockIdx.x * 256 + threadIdx.x;
    if (idx >= 16384) return;
    int n = idx >> 7, k = idx & 127;
    float v;
    if (m == 0)       v = Win[k * 128 + n];
    else if (m < 4)   v = sWl[(m - 1) * 16384 + k * 128 + n];
    else if (m < 7)   v = sWr[(m - 4) * 16384 + k * 128 + n];
    else if (m < 10)  v = l1W[(m - 7) * 16384 + k * 128 + n];
    else              v = l2W[(m - 10) * 16384 + k * 128 + n];
    __nv_bfloat16 hi = __float2bfloat16_rn(v);
    float r = v - __bfloat162float(hi);
    __nv_bfloat16 lo = __float2bfloat16_rn(r);
    uint32_t e = swoff(n, k) >> 1;
    g_whi[m * 16384 + e] = hi;
    g_wlo[m * 16384 + e] = lo;
}

// smem layout (both GEMM kernels): A_hi@0(16K) A_lo@16K W_hi@32K(32K) W_lo@64K(32K)
// ===================== input GEMM: h = [x|w] @ W_in + b_in =====================
__global__ void __launch_bounds__(NTHR, 2) k_input(
    const float* __restrict__ x, const float* __restrict__ w,
    const float* __restrict__ Win, const float* __restrict__ bin) {
    extern __shared__ char dsm[];
    __shared__ float s_b[128], s_wr[128];
    uint32_t base = smem_u32(dsm);
    uint32_t ab = (base + 1023) & ~1023u;
    char* aptr = dsm + (ab - base);
    int tid = threadIdx.x;
    int lane = tid & 31, wid = tid >> 5;
    int wR = (wid >> 2) * 32, wC = (wid & 3) * 32;
    if (tid < 128) { s_b[tid] = bin[tid]; s_wr[tid] = Win[128 * 128 + tid]; }
    copyg(g_whi, aptr + 32768, 2048);
    copyg(g_wlo, aptr + 65536, 2048);
    CPCOMMIT();
    int tile = blockIdx.x;
    int nbase = tile * TR;
    conv_tile(x, nbase, aptr, aptr + 16384);
    CPWAITG(0);
    __syncthreads();
    float C[2][4][4];
    ZEROC(C);
    gemm3(ab, ab + 16384, ab + 32768, ab + 65536, C, lane, wR, wC);
    __syncthreads();
    float* stg = (float*)aptr;
    stageC(stg, C, lane, wR, wC);
    __syncthreads();
#pragma unroll 2
    for (int i = tid; i < 2048; i += NTHR) {
        int row = i >> 5, c4 = i & 31;
        int nd = nbase + row;
        if (nd < NN) {
            float wn = w[nd];
            float4 v = ((float4*)(stg + row * 132))[c4];
            float4 o;
            o.x = v.x + s_b[c4 * 4 + 0] + wn * s_wr[c4 * 4 + 0];
            o.y = v.y + s_b[c4 * 4 + 1] + wn * s_wr[c4 * 4 + 1];
            o.z = v.z + s_b[c4 * 4 + 2] + wn * s_wr[c4 * 4 + 2];
            o.w = v.w + s_b[c4 * 4 + 3] + wn * s_wr[c4 * 4 + 3];
            ((float4*)g_h)[nd * 32 + c4] = o;
            uint2 h, l;
            split4(o, h, l);
            uint32_t off = (uint32_t)tile * 16384u + swoff(row, c4 * 4);
            *(uint2*)((char*)g_hshi + off) = h;
            *(uint2*)((char*)g_hslo + off) = l;
        }
    }
}

// ===================== fused sage+FFN block (64-row tiles, occ 2) ==============
__global__ void __launch_bounds__(NTHR, 2) k_block(
    int wlm, int wrm, int w1m, int w2m, int last,
    const int* __restrict__ batch,
    const float* __restrict__ bl, const float* __restrict__ b1,
    const float* __restrict__ b2,
    const float* __restrict__ g1, const float* __restrict__ e1,
    const float* __restrict__ g2, const float* __restrict__ e2) {
    extern __shared__ char dsm[];
    __shared__ float s_bl[128], s_b1[128], s_b2[128];
    __shared__ float s_g1[128], s_e1[128], s_g2[128], s_e2[128];
    __shared__ float red_s[4][64], red_q[4][64];
    __shared__ int s_batch[64];
    uint32_t base = smem_u32(dsm);
    uint32_t ab = (base + 1023) & ~1023u;
    char* aptr = dsm + (ab - base);
    char* p_ahi = aptr;
    char* p_alo = aptr + 16384;
    char* p_whi = aptr + 32768;
    char* p_wlo = aptr + 65536;
    int tid = threadIdx.x, lane = tid & 31, wid = tid >> 5;
    int wR = (wid >> 2) * 32, wC = (wid & 3) * 32;
    int cg = wid & 3;
    int r0 = wR + (lane >> 2);
    int c0l = (lane & 3) * 2;
    int tile = blockIdx.x;
    int nbase = tile * TR;

    copyg(g_agghi + tile * 8192, p_ahi, 1024);
    copyg(g_agglo + tile * 8192, p_alo, 1024);
    copyg(g_whi + wlm * 16384, p_whi, 2048);
    copyg(g_wlo + wlm * 16384, p_wlo, 2048);
    CPCOMMIT();
    if (tid < 128) {
        s_bl[tid] = bl[tid]; s_b1[tid] = b1[tid]; s_b2[tid] = b2[tid];
        s_g1[tid] = g1[tid]; s_e1[tid] = e1[tid];
        s_g2[tid] = g2[tid]; s_e2[tid] = e2[tid];
    }
    if (last && tid < 64) {
        int nd = nbase + tid;
        s_batch[tid] = (nd < NN) ? batch[nd] : -1;
    }
    CPWAITG(0);
    __syncthreads();

    // ---- sage GEMM 1: agg(A) @ Wl ----
    float C[2][4][4];
    ZEROC(C);
    gemm3(ab, ab + 16384, ab + 32768, ab + 65536, C, lane, wR, wC);
    __syncthreads();

    // ---- load h -> A, Wr -> W; sage GEMM 2 accumulate ----
    copyg(g_hshi + tile * 8192, p_ahi, 1024);
    copyg(g_hslo + tile * 8192, p_alo, 1024);
    copyg(g_whi + wrm * 16384, p_whi, 2048);
    copyg(g_wlo + wrm * 16384, p_wlo, 2048);
    CPCOMMIT();
    CPWAITG(0);
    __syncthreads();
    gemm3(ab, ab + 16384, ab + 32768, ab + 65536, C, lane, wR, wC);
    __syncthreads();

    // prefetch W1 under LN1
    copyg(g_whi + w1m * 16384, p_whi, 2048);
    copyg(g_wlo + w1m * 16384, p_wlo, 2048);
    CPCOMMIT();

    // ---- LN1 (+ h residual from A split), save y1 frag in regs, y1 -> A ----
    float Y[2][4][4];
    {
        float sp[4], qp[4];
#pragma unroll
        for (int mb = 0; mb < 2; mb++)
#pragma unroll
            for (int h = 0; h < 2; h++) {
                int R = r0 + mb * 16 + h * 8;
                float s = 0.f, q = 0.f;
#pragma unroll
                for (int nb = 0; nb < 4; nb++) {
                    int col = wC + c0l + nb * 8;
                    float h1;
                    float h0 = recon(p_ahi, p_alo, swoff(R, col), h1);
                    float v0 = C[mb][nb][2 * h + 0] + s_bl[col] + h0;
                    float v1 = C[mb][nb][2 * h + 1] + s_bl[col + 1] + h1;
                    C[mb][nb][2 * h + 0] = v0;
                    C[mb][nb][2 * h + 1] = v1;
                    s += v0 + v1;
                    q += v0 * v0 + v1 * v1;
                }
                sp[mb * 2 + h] = s; qp[mb * 2 + h] = q;
            }
#pragma unroll
        for (int k = 0; k < 4; k++) {
            sp[k] += __shfl_xor_sync(0xffffffffu, sp[k], 1);
            sp[k] += __shfl_xor_sync(0xffffffffu, sp[k], 2);
            qp[k] += __shfl_xor_sync(0xffffffffu, qp[k], 1);
            qp[k] += __shfl_xor_sync(0xffffffffu, qp[k], 2);
        }
        if ((lane & 3) == 0) {
#pragma unroll
            for (int k = 0; k < 4; k++) {
                int R = r0 + (k >> 1) * 16 + (k & 1) * 8;
                red_s[cg][R] = sp[k];
                red_q[cg][R] = qp[k];
            }
        }
    }
    __syncthreads();   // red ready; all warps done reading A(h)
#pragma unroll
    for (int mb = 0; mb < 2; mb++)
#pragma unroll
        for (int h = 0; h < 2; h++) {
            int R = r0 + mb * 16 + h * 8;
            float S = red_s[0][R] + red_s[1][R] + red_s[2][R] + red_s[3][R];
            float Q = red_q[0][R] + red_q[1][R] + red_q[2][R] + red_q[3][R];
            float mu = S * 0.0078125f;
            float var = Q * 0.0078125f - mu * mu;
            float inv = rsqrtf(var + 1e-5f);
#pragma unroll
            for (int nb = 0; nb < 4; nb++) {
                int col = wC + c0l + nb * 8;
                float y0 = (C[mb][nb][2 * h + 0] - mu) * inv * s_g1[col] + s_e1[col];
                float y1v = (C[mb][nb][2 * h + 1] - mu) * inv * s_g1[col + 1] + s_e1[col + 1];
                Y[mb][nb][2 * h + 0] = y0;
                Y[mb][nb][2 * h + 1] = y1v;
                __nv_bfloat16 h0 = __float2bfloat16_rn(y0);
                __nv_bfloat16 h1 = __float2bfloat16_rn(y1v);
                __nv_bfloat162 HP; HP.x = h0; HP.y = h1;
                __nv_bfloat162 LP = __floats2bfloat162_rn(y0 - __bfloat162float(h0),
                                                          y1v - __bfloat162float(h1));
                uint32_t off = swoff(R, col);
                *(uint32_t*)(p_ahi + off) = *(uint32_t*)&HP;
                *(uint32_t*)(p_alo + off) = *(uint32_t*)&LP;
            }
        }
    CPWAITG(0);
    __syncthreads();

    // ---- FFN GEMM 1: y1(A) @ W1 ----
    ZEROC(C);
    gemm3(ab, ab + 16384, ab + 32768, ab + 65536, C, lane, wR, wC);
    __syncthreads();

    copyg(g_whi + w2m * 16384, p_whi, 2048);
    copyg(g_wlo + w2m * 16384, p_wlo, 2048);
    CPCOMMIT();

    // elu(C + b1) -> split into A (y1 kept in regs)
#pragma unroll
    for (int mb = 0; mb < 2; mb++)
#pragma unroll
        for (int nb = 0; nb < 4; nb++) {
            int col = wC + c0l + nb * 8;
#pragma unroll
            for (int h = 0; h < 2; h++) {
                int R = r0 + mb * 16 + h * 8;
                float t0 = C[mb][nb][2 * h + 0] + s_b1[col];
                float t1 = C[mb][nb][2 * h + 1] + s_b1[col + 1];
                t0 = t0 > 0.f ? t0 : expm1f(t0);
                t1 = t1 > 0.f ? t1 : expm1f(t1);
                __nv_bfloat16 h0 = __float2bfloat16_rn(t0);
                __nv_bfloat16 h1 = __float2bfloat16_rn(t1);
                __nv_bfloat162 HP; HP.x = h0; HP.y = h1;
                __nv_bfloat162 LP = __floats2bfloat162_rn(t0 - __bfloat162float(h0),
                                                          t1 - __bfloat162float(h1));
                uint32_t off = swoff(R, col);
                *(uint32_t*)(p_ahi + off) = *(uint32_t*)&HP;
                *(uint32_t*)(p_alo + off) = *(uint32_t*)&LP;
            }
        }
    CPWAITG(0);
    __syncthreads();

    // ---- FFN GEMM 2: elu(A) @ W2 ----
    ZEROC(C);
    gemm3(ab, ab + 16384, ab + 32768, ab + 65536, C, lane, wR, wC);

    // ---- LN2 (+ y1 residual from regs) ----
    {
        float sp[4], qp[4];
#pragma unroll
        for (int mb = 0; mb < 2; mb++)
#pragma unroll
            for (int h = 0; h < 2; h++) {
                float s = 0.f, q = 0.f;
#pragma unroll
                for (int nb = 0; nb < 4; nb++) {
                    int col = wC + c0l + nb * 8;
                    float v0 = C[mb][nb][2 * h + 0] + s_b2[col] + Y[mb][nb][2 * h + 0];
                    float v1 = C[mb][nb][2 * h + 1] + s_b2[col + 1] + Y[mb][nb][2 * h + 1];
                    C[mb][nb][2 * h + 0] = v0;
                    C[mb][nb][2 * h + 1] = v1;
                    s += v0 + v1;
                    q += v0 * v0 + v1 * v1;
                }
                sp[mb * 2 + h] = s; qp[mb * 2 + h] = q;
            }
#pragma unroll
        for (int k = 0; k < 4; k++) {
            sp[k] += __shfl_xor_sync(0xffffffffu, sp[k], 1);
            sp[k] += __shfl_xor_sync(0xffffffffu, sp[k], 2);
            qp[k] += __shfl_xor_sync(0xffffffffu, qp[k], 1);
            qp[k] += __shfl_xor_sync(0xffffffffu, qp[k], 2);
        }
        if ((lane & 3) == 0) {
#pragma unroll
            for (int k = 0; k < 4; k++) {
                int R = r0 + (k >> 1) * 16 + (k & 1) * 8;
                red_s[cg][R] = sp[k];
                red_q[cg][R] = qp[k];
            }
        }
    }
    __syncthreads();   // red ready; A/W dead (gemm2' done everywhere)
    float* stg = (float*)aptr;   // 64*132*4 = 33.8KB over A + 1KB of W
#pragma unroll
    for (int mb = 0; mb < 2; mb++)
#pragma unroll
        for (int h = 0; h < 2; h++) {
            int R = r0 + mb * 16 + h * 8;
            float S = red_s[0][R] + red_s[1][R] + red_s[2][R] + red_s[3][R];
            float Q = red_q[0][R] + red_q[1][R] + red_q[2][R] + red_q[3][R];
            float mu = S * 0.0078125f;
            float var = Q * 0.0078125f - mu * mu;
            float inv = rsqrtf(var + 1e-5f);
#pragma unroll
            for (int nb = 0; nb < 4; nb++) {
                int col = wC + c0l + nb * 8;
                float o0 = (C[mb][nb][2 * h + 0] - mu) * inv * s_g2[col] + s_e2[col];
                float o1 = (C[mb][nb][2 * h + 1] - mu) * inv * s_g2[col + 1] + s_e2[col + 1];
                *(float2*)(stg + R * 132 + col) = make_float2(o0, o1);
            }
        }
    __syncthreads();
    if (!last) {
#pragma unroll 2
        for (int i = tid; i < 2048; i += NTHR) {
            int row = i >> 5, c4 = i & 31;
            int nd = nbase + row;
            if (nd < NN) {
                float4 v = ((float4*)(stg + row * 132))[c4];
                ((float4*)g_h)[nd * 32 + c4] = v;
                uint2 h, l;
                split4(v, h, l);
                uint32_t off = (uint32_t)tile * 16384u + swoff(row, c4 * 4);
                *(uint2*)((char*)g_hshi + off) = h;
                *(uint2*)((char*)g_hslo + off) = l;
            }
        }
    } else {
        // final layer: per-graph partial sums (batch sorted); halves of 32 rows
        int f = tid & 127, q = tid >> 7;
        int rbeg = q * 32;
        int cur = s_batch[rbeg];
        float acc = 0.f;
#pragma unroll 4
        for (int r = rbeg; r < rbeg + 32; r++) {
            int bg = s_batch[r];
            if (bg < 0) break;
            if (bg != cur) {
                atomicAdd(&g_gm[cur * FD + f], acc);
                acc = 0.f;
                cur = bg;
            }
            acc += stg[r * 132 + f];
        }
        if (cur >= 0) atomicAdd(&g_gm[cur * FD + f], acc);
    }
}

// ===================== head =====================
__global__ void __launch_bounds__(128, 1) k_pool(
    const float* __restrict__ mdfW, const float* __restrict__ mdfb,
    const float* __restrict__ pg1, const float* __restrict__ pb1,
    const float* __restrict__ W1, const float* __restrict__ b1,
    const float* __restrict__ W2, const float* __restrict__ b2,
    const float* __restrict__ pg2, const float* __restrict__ pb2,
    float* __restrict__ out) {
    extern __shared__ float ws[];
    __shared__ float vm[128], hh[128], tt[128], red[8];
    int f = threadIdx.x, lane = f & 31, wp = f >> 5;
    for (int i = f; i < 16384; i += 128) {
        ws[i] = mdfW[i];
        ws[16384 + i] = W1[i];
        ws[32768 + i] = W2[i];
    }
    float c_mb = mdfb[f], c_g1 = pg1[f], c_b1 = pb1[f];
    float c_bl1 = b1[f], c_bl2 = b2[f], c_g2 = pg2[f], c_b2 = pb2[f];
    __syncthreads();
    for (int gi = 0; gi < 8; gi++) {
        int g = blockIdx.x * 8 + gi;
        vm[f] = g_gm[g * FD + f] / g_cntf[g];
        __syncthreads();
        float p = 0.f;
#pragma unroll 4
        for (int k = 0; k < 128; k++) p = fmaf(vm[k], ws[k * 128 + f], p);
        p += c_mb;
        float s = p, q = p * p;
#pragma unroll
        for (int off = 16; off; off >>= 1) {
            s += __shfl_xor_sync(0xffffffffu, s, off);
            q += __shfl_xor_sync(0xffffffffu, q, off);
        }
        if (lane == 0) { red[wp] = s; red[4 + wp] = q; }
        __syncthreads();
        s = red[0] + red[1] + red[2] + red[3];
        q = red[4] + red[5] + red[6] + red[7];
        float mu = s * 0.0078125f;
        float var = q * 0.0078125f - mu * mu;
        float inv = rsqrtf(var + 1e-5f);
        float h0 = (p - mu) * inv * c_g1 + c_b1;
        __syncthreads();
        hh[f] = h0;
        __syncthreads();
        float a = 0.f;
#pragma unroll 4
        for (int k = 0; k < 128; k++) a = fmaf(hh[k], ws[16384 + k * 128 + f], a);
        a += c_bl1;
        a = a > 0.f ? a : expm1f(a);
        tt[f] = a;
        __syncthreads();
        float y = 0.f;
#pragma unroll 4
        for (int k = 0; k < 128; k++) y = fmaf(tt[k], ws[32768 + k * 128 + f], y);
        y += c_bl2;
        float v2 = y + h0;
        s = v2; q = v2 * v2;
#pragma unroll
        for (int off = 16; off; off >>= 1) {
            s += __shfl_xor_sync(0xffffffffu, s, off);
            q += __shfl_xor_sync(0xffffffffu, q, off);
        }
        if (lane == 0) { red[wp] = s; red[4 + wp] = q; }
        __syncthreads();
        s = red[0] + red[1] + red[2] + red[3];
        q = red[4] + red[5] + red[6] + red[7];
        mu = s * 0.0078125f;
        var = q * 0.0078125f - mu * mu;
        inv = rsqrtf(var + 1e-5f);
        out[g * FD + f] = (v2 - mu) * inv * c_g2 + c_b2;
        __syncthreads();
    }
}

// ===================== launcher (setup-phase fork) =====================
extern "C" void kernel_launch(void* const* d_in, const int* in_sizes, int n_in,
                              void* d_out, int out_size) {
    const float* x    = (const float*)d_in[0];
    const float* w    = (const float*)d_in[1];
    const int*   ei   = (const int*)d_in[2];
    const int*   batch= (const int*)d_in[3];
    const float* Win  = (const float*)d_in[4];
    const float* bin  = (const float*)d_in[5];
    const float* sWl  = (const float*)d_in[6];
    const float* sbl  = (const float*)d_in[7];
    const float* sWr  = (const float*)d_in[8];
    const float* ln1g = (const float*)d_in[9];
    const float* ln1b = (const float*)d_in[10];
    const float* l1W  = (const float*)d_in[11];
    const float* l1b  = (const float*)d_in[12];
    const float* l2W  = (const float*)d_in[13];
    const float* l2b  = (const float*)d_in[14];
    const float* ln2g = (const float*)d_in[15];
    const float* ln2b = (const float*)d_in[16];
    const float* mdfW = (const float*)d_in[17];
    const float* mdfb = (const float*)d_in[18];
    const float* pg1  = (const float*)d_in[19];
    const float* pb1  = (const float*)d_in[20];
    const float* pW1  = (const float*)d_in[21];
    const float* pb1l = (const float*)d_in[22];
    const float* pW2  = (const float*)d_in[23];
    const float* pb2l = (const float*)d_in[24];
    const float* pg2  = (const float*)d_in[25];
    const float* pb2  = (const float*)d_in[26];

    const int SM_GEMM = 1024 + 98304;   // A(32K) + W(64K) + align
    const int SM_POOL = 49152 * 4;
    cudaFuncSetAttribute(k_input, cudaFuncAttributeMaxDynamicSharedMemorySize, SM_GEMM);
    cudaFuncSetAttribute(k_block, cudaFuncAttributeMaxDynamicSharedMemorySize, SM_GEMM);
    cudaFuncSetAttribute(k_pool,  cudaFuncAttributeMaxDynamicSharedMemorySize, SM_POOL);

    cudaStream_t s2;
    cudaStreamCreateWithFlags(&s2, cudaStreamNonBlocking);
    cudaEvent_t evFork, evCSR;
    cudaEventCreateWithFlags(&evFork, cudaEventDisableTiming);
    cudaEventCreateWithFlags(&evCSR, cudaEventDisableTiming);

    // fork: CSR build on s2, weights + input GEMM on stream0
    k_zero<<<512, 256>>>();
    cudaEventRecord(evFork, 0);
    cudaStreamWaitEvent(s2, evFork, 0);

    k_count<<<(NE + 255) / 256, 256, 0, s2>>>(ei, batch);
    k_scan1<<<(NN + 511) / 512, 512, 0, s2>>>();
    k_scan23<<<(NN + 255) / 256, 256, 0, s2>>>();
    k_fill<<<(NE + 255) / 256, 256, 0, s2>>>(ei);
    cudaEventRecord(evCSR, s2);

    k_wprep<<<dim3(64, 13), 256>>>(Win, sWl, sWr, l1W, l2W);
    k_input<<<NT2, NTHR, SM_GEMM>>>(x, w, Win, bin);
    cudaStreamWaitEvent(0, evCSR, 0);   // join before first gather

    for (int l = 0; l < 3; l++) {
        k_gather<<<(NN * 32 + 255) / 256, 256>>>();
        k_block<<<NT2, NTHR, SM_GEMM>>>(1 + l, 4 + l, 7 + l, 10 + l, (l == 2),
                                        batch,
                                        sbl + l * FD, l1b + l * FD, l2b + l * FD,
                                        ln1g + l * FD, ln1b + l * FD,
                                        ln2g + l * FD, ln2b + l * FD);
    }

    k_pool<<<NG / 8, 128, SM_POOL>>>(mdfW, mdfb, pg1, pb1, pW1, pb1l,
                                     pW2, pb2l, pg2, pb2, (float*)d_out);
}

// round 15
// speedup vs baseline: 1.3028x; 1.0439x over previous
#include <cuda_runtime.h>
#include <cuda_bf16.h>
#include <math.h>
#include <stdint.h>

#define NN 100000
#define NE 1600000
#define NG 1024
#define FD 128
#define TR 64               // tile rows
#define NT2 1563            // ceil(NN/64)
#define NTHR 256

// ===================== scratch (device globals) =====================
__device__ float g_degf[NN];
__device__ int   g_deg[NN];
__device__ int   g_rowstart[NN + 1];
__device__ int   g_cursor[NN];
__device__ int   g_csrsrc[NE];
__device__ int   g_cnti[NG];
__device__ float g_cntf[NG];
__device__ float g_gm[NG * FD];
__device__ int   g_bsum[256];
// split activations in 64-row tile-swizzled layout (16KB per tile per component)
__device__ __nv_bfloat16 g_agghi[NT2 * 8192];
__device__ __nv_bfloat16 g_agglo[NT2 * 8192];
__device__ __nv_bfloat16 g_hshi[NT2 * 8192];
__device__ __nv_bfloat16 g_hslo[NT2 * 8192];
// pre-transposed, split, swizzled weights: 13 matrices of 128x128 bf16
// m: 0=Win, 1..3=sage_Wl, 4..6=sage_Wr, 7..9=lin1, 10..12=lin2
__device__ __nv_bfloat16 g_whi[13 * 16384];
__device__ __nv_bfloat16 g_wlo[13 * 16384];

// ===================== helpers =====================
__device__ __forceinline__ uint32_t smem_u32(const void* p) {
    uint32_t a;
    asm("{ .reg .u64 t; cvta.to.shared.u64 t, %1; cvt.u32.u64 %0, t; }" : "=r"(a) : "l"(p));
    return a;
}

// XOR-swizzled byte offset inside a [rows][128 cols] bf16 tile (256B/row).
__device__ __forceinline__ uint32_t swoff(int row, int col) {
    return (uint32_t)row * 256u
         + ((uint32_t)(((col >> 3) ^ (row & 7)) & 15) << 4)
         + ((uint32_t)(col & 7) << 1);
}

#define LDM4(r0, r1, r2, r3, a) \
    asm volatile("ldmatrix.sync.aligned.m8n8.x4.shared.b16 {%0,%1,%2,%3}, [%4];" \
        : "=r"(r0), "=r"(r1), "=r"(r2), "=r"(r3) : "r"(a))

#define MMA16(c, a, b0, b1) \
    asm volatile("mma.sync.aligned.m16n8k16.row.col.f32.bf16.bf16.f32 " \
        "{%0,%1,%2,%3},{%4,%5,%6,%7},{%8,%9},{%0,%1,%2,%3};" \
        : "+f"((c)[0]), "+f"((c)[1]), "+f"((c)[2]), "+f"((c)[3]) \
        : "r"((a)[0]), "r"((a)[1]), "r"((a)[2]), "r"((a)[3]), "r"(b0), "r"(b1))

__device__ __forceinline__ void split4(float4 v, uint2& hi, uint2& lo) {
    __nv_bfloat16 hx = __float2bfloat16_rn(v.x), hy = __float2bfloat16_rn(v.y);
    __nv_bfloat16 hz = __float2bfloat16_rn(v.z), hw = __float2bfloat16_rn(v.w);
    float rx = v.x - __bfloat162float(hx), ry = v.y - __bfloat162float(hy);
    float rz = v.z - __bfloat162float(hz), rw = v.w - __bfloat162float(hw);
    __nv_bfloat162 H0; H0.x = hx; H0.y = hy;
    __nv_bfloat162 H1; H1.x = hz; H1.y = hw;
    __nv_bfloat162 L0 = __floats2bfloat162_rn(rx, ry);
    __nv_bfloat162 L1 = __floats2bfloat162_rn(rz, rw);
    hi.x = *(uint32_t*)&H0; hi.y = *(uint32_t*)&H1;
    lo.x = *(uint32_t*)&L0; lo.y = *(uint32_t*)&L1;
}

__device__ __forceinline__ float recon(const char* hi, const char* lo, uint32_t off,
                                       float& v1) {
    uint32_t uh = *(const uint32_t*)(hi + off);
    uint32_t ul = *(const uint32_t*)(lo + off);
    __nv_bfloat162 bh = *(__nv_bfloat162*)&uh;
    __nv_bfloat162 bl = *(__nv_bfloat162*)&ul;
    v1 = __bfloat162float(bh.y) + __bfloat162float(bl.y);
    return __bfloat162float(bh.x) + __bfloat162float(bl.x);
}

// fp32 global 64-row tile -> split bf16 swizzled smem (k_input only)
__device__ __forceinline__ void conv_tile(const float* __restrict__ src, int nbase,
                                          char* ahi, char* alo) {
#pragma unroll 2
    for (int i = threadIdx.x; i < 2048; i += NTHR) {
        int row = i >> 5, c4 = i & 31;
        int node = nbase + row;
        float4 v = make_float4(0.f, 0.f, 0.f, 0.f);
        if (node < NN) v = ((const float4*)src)[node * 32 + c4];
        uint2 h, l;
        split4(v, h, l);
        uint32_t off = swoff(row, c4 * 4);
        *(uint2*)(ahi + off) = h;
        *(uint2*)(alo + off) = l;
    }
}

// cp.async global -> smem (flat copy; layouts match)
__device__ __forceinline__ void copyg(const __nv_bfloat16* src, char* dst, int n16) {
    uint32_t d = smem_u32(dst);
    for (int i = threadIdx.x; i < n16; i += NTHR)
        asm volatile("cp.async.cg.shared.global [%0], [%1], 16;"
                     :: "r"(d + i * 16), "l"(src + i * 8) : "memory");
}
#define CPCOMMIT() asm volatile("cp.async.commit_group;" ::: "memory")
#define CPWAITG(n) asm volatile("cp.async.wait_group %0;" :: "n"(n) : "memory")

// warp-tiled 3-term split GEMM: C[32x32] += (Ahi+Alo)@(Whi+Wlo) (dropping lo*lo)
__device__ __forceinline__ void gemm3(uint32_t ahi, uint32_t alo,
                                      uint32_t whi, uint32_t wlo,
                                      float C[2][4][4], int lane, int wR, int wC) {
    int arow = (lane & 7) + ((lane >> 3) & 1) * 8;
    int acolo = ((lane >> 4) & 1) * 8;
    int brow = (lane & 7) + ((lane >> 4) & 1) * 8;
    int bcolo = ((lane >> 3) & 1) * 8;
#pragma unroll
    for (int kk = 0; kk < 8; kk++) {
        int kbase = kk * 16;
        uint32_t ah[2][4], al[2][4];
#pragma unroll
        for (int mb = 0; mb < 2; mb++) {
            uint32_t oa = swoff(wR + mb * 16 + arow, kbase + acolo);
            LDM4(ah[mb][0], ah[mb][1], ah[mb][2], ah[mb][3], ahi + oa);
            LDM4(al[mb][0], al[mb][1], al[mb][2], al[mb][3], alo + oa);
        }
#pragma unroll
        for (int nbp = 0; nbp < 2; nbp++) {
            uint32_t ob = swoff(wC + nbp * 16 + brow, kbase + bcolo);
            uint32_t bh[4], bl[4];
            LDM4(bh[0], bh[1], bh[2], bh[3], whi + ob);
            LDM4(bl[0], bl[1], bl[2], bl[3], wlo + ob);
#pragma unroll
            for (int mb = 0; mb < 2; mb++) {
                MMA16(C[mb][2 * nbp],     ah[mb], bh[0], bh[1]);
                MMA16(C[mb][2 * nbp + 1], ah[mb], bh[2], bh[3]);
                MMA16(C[mb][2 * nbp],     ah[mb], bl[0], bl[1]);
                MMA16(C[mb][2 * nbp + 1], ah[mb], bl[2], bl[3]);
                MMA16(C[mb][2 * nbp],     al[mb], bh[0], bh[1]);
                MMA16(C[mb][2 * nbp + 1], al[mb], bh[2], bh[3]);
            }
        }
    }
}

#define ZEROC(C) do { \
    _Pragma("unroll") for (int _a = 0; _a < 2; _a++) \
    _Pragma("unroll") for (int _b = 0; _b < 4; _b++) \
    _Pragma("unroll") for (int _c = 0; _c < 4; _c++) (C)[_a][_b][_c] = 0.f; \
} while (0)

// stage C frags into fp32 smem [64][132]
__device__ __forceinline__ void stageC(float* stg, float C[2][4][4], int lane, int wR, int wC) {
    int r0 = wR + (lane >> 2);
    int c0 = wC + (lane & 3) * 2;
#pragma unroll
    for (int mb = 0; mb < 2; mb++) {
#pragma unroll
        for (int nb = 0; nb < 4; nb++) {
            int row = r0 + mb * 16;
            int col = c0 + nb * 8;
            *(float2*)(stg + row * 132 + col) = make_float2(C[mb][nb][0], C[mb][nb][1]);
            *(float2*)(stg + (row + 8) * 132 + col) = make_float2(C[mb][nb][2], C[mb][nb][3]);
        }
    }
}

// ===================== setup kernels =====================
__global__ void k_zero() {
    int i = blockIdx.x * blockDim.x + threadIdx.x;
    if (i < NN) g_deg[i] = 0;
    if (i < NG) g_cnti[i] = 0;
    if (i < NG * FD) g_gm[i] = 0.f;
}
__global__ void k_count(const int* __restrict__ ei, const int* __restrict__ batch) {
    int i = blockIdx.x * blockDim.x + threadIdx.x;
    if (i < NE) atomicAdd(&g_deg[ei[NE + i]], 1);
    if (i < NN) atomicAdd(&g_cnti[batch[i]], 1);
}
__global__ void k_scan1() {
    __shared__ int s[512];
    int i = blockIdx.x * 512 + threadIdx.x;
    int v = (i < NN) ? g_deg[i] : 0;
    s[threadIdx.x] = v;
    __syncthreads();
#pragma unroll
    for (int off = 1; off < 512; off <<= 1) {
        int t = (threadIdx.x >= off) ? s[threadIdx.x - off] : 0;
        __syncthreads();
        s[threadIdx.x] += t;
        __syncthreads();
    }
    if (i < NN) g_rowstart[i + 1] = s[threadIdx.x];
    if (threadIdx.x == 511) g_bsum[blockIdx.x] = s[511];
}
__global__ void k_scan23() {
    __shared__ int pre[256];
    const int nb = (NN + 511) / 512;  // 196
    int v = (threadIdx.x < nb) ? g_bsum[threadIdx.x] : 0;
    pre[threadIdx.x] = v;
    __syncthreads();
#pragma unroll
    for (int off = 1; off < 256; off <<= 1) {
        int t = (threadIdx.x >= off) ? pre[threadIdx.x - off] : 0;
        __syncthreads();
        pre[threadIdx.x] += t;
        __syncthreads();
    }
    pre[threadIdx.x] -= v;  // exclusive
    __syncthreads();
    int i = blockIdx.x * blockDim.x + threadIdx.x;
    if (i >= NN) return;
    int r = g_rowstart[i + 1] + pre[i >> 9];
    g_rowstart[i + 1] = r;
    g_cursor[i] = r - g_deg[i];
    g_degf[i] = fmaxf((float)g_deg[i], 1.f);
    if (i == 0) g_rowstart[0] = 0;
    if (i < NG) g_cntf[i] = fmaxf((float)g_cnti[i], 1.f);
}
__global__ void k_fill(const int* __restrict__ ei) {
    int e = blockIdx.x * blockDim.x + threadIdx.x;
    if (e >= NE) return;
    int src = ei[e];
    int dst = ei[NE + e];
    int pos = atomicAdd(&g_cursor[dst], 1);
    g_csrsrc[pos] = src;
}
// gather: mean over incoming edges, reading bf16 HI of h (halved bytes).
// one 8B load per lane per edge, same MLP as the fp32 version.
__global__ void k_gather() {
    int gw = (blockIdx.x * blockDim.x + threadIdx.x) >> 5;
    int lane = threadIdx.x & 31;
    if (gw >= NN) return;
    int beg = g_rowstart[gw], end = g_rowstart[gw + 1];
    float4 acc = make_float4(0.f, 0.f, 0.f, 0.f);
    int gr = lane >> 1;             // 16B-granule index of col = lane*4
    int by = (lane & 1) * 8;        // byte within granule
    const char* hs = (const char*)g_hshi;
    int e = beg;
    for (; e + 4 <= end; e += 4) {
        int s0 = g_csrsrc[e], s1 = g_csrsrc[e + 1], s2 = g_csrsrc[e + 2], s3 = g_csrsrc[e + 3];
        int r0 = s0 & 63, r1 = s1 & 63, r2 = s2 & 63, r3 = s3 & 63;
        uint32_t o0 = ((uint32_t)(s0 >> 6)) * 16384u + (uint32_t)r0 * 256u
                    + (uint32_t)(((gr ^ (r0 & 7)) & 15) << 4) + by;
        uint32_t o1 = ((uint32_t)(s1 >> 6)) * 16384u + (uint32_t)r1 * 256u
                    + (uint32_t)(((gr ^ (r1 & 7)) & 15) << 4) + by;
        uint32_t o2 = ((uint32_t)(s2 >> 6)) * 16384u + (uint32_t)r2 * 256u
                    + (uint32_t)(((gr ^ (r2 & 7)) & 15) << 4) + by;
        uint32_t o3 = ((uint32_t)(s3 >> 6)) * 16384u + (uint32_t)r3 * 256u
                    + (uint32_t)(((gr ^ (r3 & 7)) & 15) << 4) + by;
        uint2 u0 = *(const uint2*)(hs + o0);
        uint2 u1 = *(const uint2*)(hs + o1);
        uint2 u2 = *(const uint2*)(hs + o2);
        uint2 u3 = *(const uint2*)(hs + o3);
        float2 a0 = __bfloat1622float2(*(__nv_bfloat162*)&u0.x);
        float2 b0 = __bfloat1622float2(*(__nv_bfloat162*)&u0.y);
        float2 a1 = __bfloat1622float2(*(__nv_bfloat162*)&u1.x);
        float2 b1 = __bfloat1622float2(*(__nv_bfloat162*)&u1.y);
        float2 a2 = __bfloat1622float2(*(__nv_bfloat162*)&u2.x);
        float2 b2 = __bfloat1622float2(*(__nv_bfloat162*)&u2.y);
        float2 a3 = __bfloat1622float2(*(__nv_bfloat162*)&u3.x);
        float2 b3 = __bfloat1622float2(*(__nv_bfloat162*)&u3.y);
        acc.x += (a0.x + a1.x) + (a2.x + a3.x);
        acc.y += (a0.y + a1.y) + (a2.y + a3.y);
        acc.z += (b0.x + b1.x) + (b2.x + b3.x);
        acc.w += (b0.y + b1.y) + (b2.y + b3.y);
    }
    for (; e < end; ++e) {
        int s0 = g_csrsrc[e];
        int r0 = s0 & 63;
        uint32_t o0 = ((uint32_t)(s0 >> 6)) * 16384u + (uint32_t)r0 * 256u
                    + (uint32_t)(((gr ^ (r0 & 7)) & 15) << 4) + by;
        uint2 u0 = *(const uint2*)(hs + o0);
        float2 a0 = __bfloat1622float2(*(__nv_bfloat162*)&u0.x);
        float2 b0 = __bfloat1622float2(*(__nv_bfloat162*)&u0.y);
        acc.x += a0.x; acc.y += a0.y; acc.z += b0.x; acc.w += b0.y;
    }
    float inv = 1.f / g_degf[gw];
    acc.x *= inv; acc.y *= inv; acc.z *= inv; acc.w *= inv;
    uint2 h, l;
    split4(acc, h, l);
    int tile = gw >> 6, row = gw & 63;
    uint32_t off = (uint32_t)tile * 16384u + swoff(row, lane * 4);
    *(uint2*)((char*)g_agghi + off) = h;
    *(uint2*)((char*)g_agglo + off) = l;
}
// weight prep: transpose to [N,K], split hi/lo bf16, swizzled (13 matrices)
__global__ void k_wprep(const float* __restrict__ Win, const float* __restrict__ sWl,
                        const float* __restrict__ sWr, const float* __restrict__ l1W,
                        const float* __restrict__ l2W) {
    int m = blockIdx.y;
    int idx = blockIdx.x * 256 + threadIdx.x;
    if (idx >= 16384) return;
    int n = idx >> 7, k = idx & 127;
    float v;
    if (m == 0)       v = Win[k * 128 + n];
    else if (m < 4)   v = sWl[(m - 1) * 16384 + k * 128 + n];
    else if (m < 7)   v = sWr[(m - 4) * 16384 + k * 128 + n];
    else if (m < 10)  v = l1W[(m - 7) * 16384 + k * 128 + n];
    else              v = l2W[(m - 10) * 16384 + k * 128 + n];
    __nv_bfloat16 hi = __float2bfloat16_rn(v);
    float r = v - __bfloat162float(hi);
    __nv_bfloat16 lo = __float2bfloat16_rn(r);
    uint32_t e = swoff(n, k) >> 1;
    g_whi[m * 16384 + e] = hi;
    g_wlo[m * 16384 + e] = lo;
}

// smem layout (both GEMM kernels): A_hi@0(16K) A_lo@16K W_hi@32K(32K) W_lo@64K(32K)
// ===================== input GEMM: h = [x|w] @ W_in + b_in =====================
__global__ void __launch_bounds__(NTHR, 2) k_input(
    const float* __restrict__ x, const float* __restrict__ w,
    const float* __restrict__ Win, const float* __restrict__ bin) {
    extern __shared__ char dsm[];
    __shared__ float s_b[128], s_wr[128];
    uint32_t base = smem_u32(dsm);
    uint32_t ab = (base + 1023) & ~1023u;
    char* aptr = dsm + (ab - base);
    int tid = threadIdx.x;
    int lane = tid & 31, wid = tid >> 5;
    int wR = (wid >> 2) * 32, wC = (wid & 3) * 32;
    if (tid < 128) { s_b[tid] = bin[tid]; s_wr[tid] = Win[128 * 128 + tid]; }
    copyg(g_whi, aptr + 32768, 2048);
    copyg(g_wlo, aptr + 65536, 2048);
    CPCOMMIT();
    int tile = blockIdx.x;
    int nbase = tile * TR;
    conv_tile(x, nbase, aptr, aptr + 16384);
    CPWAITG(0);
    __syncthreads();
    float C[2][4][4];
    ZEROC(C);
    gemm3(ab, ab + 16384, ab + 32768, ab + 65536, C, lane, wR, wC);
    __syncthreads();
    float* stg = (float*)aptr;
    stageC(stg, C, lane, wR, wC);
    __syncthreads();
#pragma unroll 2
    for (int i = tid; i < 2048; i += NTHR) {
        int row = i >> 5, c4 = i & 31;
        int nd = nbase + row;
        if (nd < NN) {
            float wn = w[nd];
            float4 v = ((float4*)(stg + row * 132))[c4];
            float4 o;
            o.x = v.x + s_b[c4 * 4 + 0] + wn * s_wr[c4 * 4 + 0];
            o.y = v.y + s_b[c4 * 4 + 1] + wn * s_wr[c4 * 4 + 1];
            o.z = v.z + s_b[c4 * 4 + 2] + wn * s_wr[c4 * 4 + 2];
            o.w = v.w + s_b[c4 * 4 + 3] + wn * s_wr[c4 * 4 + 3];
            uint2 h, l;
            split4(o, h, l);
            uint32_t off = (uint32_t)tile * 16384u + swoff(row, c4 * 4);
            *(uint2*)((char*)g_hshi + off) = h;
            *(uint2*)((char*)g_hslo + off) = l;
        }
    }
}

// ===================== fused sage+FFN block (64-row tiles, occ 2) ==============
__global__ void __launch_bounds__(NTHR, 2) k_block(
    int wlm, int wrm, int w1m, int w2m, int last,
    const int* __restrict__ batch,
    const float* __restrict__ bl, const float* __restrict__ b1,
    const float* __restrict__ b2,
    const float* __restrict__ g1, const float* __restrict__ e1,
    const float* __restrict__ g2, const float* __restrict__ e2) {
    extern __shared__ char dsm[];
    __shared__ float s_bl[128], s_b1[128], s_b2[128];
    __shared__ float s_g1[128], s_e1[128], s_g2[128], s_e2[128];
    __shared__ float red_s[4][64], red_q[4][64];
    __shared__ int s_batch[64];
    uint32_t base = smem_u32(dsm);
    uint32_t ab = (base + 1023) & ~1023u;
    char* aptr = dsm + (ab - base);
    char* p_ahi = aptr;
    char* p_alo = aptr + 16384;
    char* p_whi = aptr + 32768;
    char* p_wlo = aptr + 65536;
    int tid = threadIdx.x, lane = tid & 31, wid = tid >> 5;
    int wR = (wid >> 2) * 32, wC = (wid & 3) * 32;
    int cg = wid & 3;
    int r0 = wR + (lane >> 2);
    int c0l = (lane & 3) * 2;
    int tile = blockIdx.x;
    int nbase = tile * TR;

    copyg(g_agghi + tile * 8192, p_ahi, 1024);
    copyg(g_agglo + tile * 8192, p_alo, 1024);
    copyg(g_whi + wlm * 16384, p_whi, 2048);
    copyg(g_wlo + wlm * 16384, p_wlo, 2048);
    CPCOMMIT();
    if (tid < 128) {
        s_bl[tid] = bl[tid]; s_b1[tid] = b1[tid]; s_b2[tid] = b2[tid];
        s_g1[tid] = g1[tid]; s_e1[tid] = e1[tid];
        s_g2[tid] = g2[tid]; s_e2[tid] = e2[tid];
    }
    if (last && tid < 64) {
        int nd = nbase + tid;
        s_batch[tid] = (nd < NN) ? batch[nd] : -1;
    }
    CPWAITG(0);
    __syncthreads();

    // ---- sage GEMM 1: agg(A) @ Wl ----
    float C[2][4][4];
    ZEROC(C);
    gemm3(ab, ab + 16384, ab + 32768, ab + 65536, C, lane, wR, wC);
    __syncthreads();

    // ---- load h -> A, Wr -> W; sage GEMM 2 accumulate ----
    copyg(g_hshi + tile * 8192, p_ahi, 1024);
    copyg(g_hslo + tile * 8192, p_alo, 1024);
    copyg(g_whi + wrm * 16384, p_whi, 2048);
    copyg(g_wlo + wrm * 16384, p_wlo, 2048);
    CPCOMMIT();
    CPWAITG(0);
    __syncthreads();
    gemm3(ab, ab + 16384, ab + 32768, ab + 65536, C, lane, wR, wC);
    __syncthreads();

    // prefetch W1 under LN1
    copyg(g_whi + w1m * 16384, p_whi, 2048);
    copyg(g_wlo + w1m * 16384, p_wlo, 2048);
    CPCOMMIT();

    // ---- LN1 (+ h residual from A split), save y1 frag in regs, y1 -> A ----
    float Y[2][4][4];
    {
        float sp[4], qp[4];
#pragma unroll
        for (int mb = 0; mb < 2; mb++)
#pragma unroll
            for (int h = 0; h < 2; h++) {
                int R = r0 + mb * 16 + h * 8;
                float s = 0.f, q = 0.f;
#pragma unroll
                for (int nb = 0; nb < 4; nb++) {
                    int col = wC + c0l + nb * 8;
                    float h1;
                    float h0 = recon(p_ahi, p_alo, swoff(R, col), h1);
                    float v0 = C[mb][nb][2 * h + 0] + s_bl[col] + h0;
                    float v1 = C[mb][nb][2 * h + 1] + s_bl[col + 1] + h1;
                    C[mb][nb][2 * h + 0] = v0;
                    C[mb][nb][2 * h + 1] = v1;
                    s += v0 + v1;
                    q += v0 * v0 + v1 * v1;
                }
                sp[mb * 2 + h] = s; qp[mb * 2 + h] = q;
            }
#pragma unroll
        for (int k = 0; k < 4; k++) {
            sp[k] += __shfl_xor_sync(0xffffffffu, sp[k], 1);
            sp[k] += __shfl_xor_sync(0xffffffffu, sp[k], 2);
            qp[k] += __shfl_xor_sync(0xffffffffu, qp[k], 1);
            qp[k] += __shfl_xor_sync(0xffffffffu, qp[k], 2);
        }
        if ((lane & 3) == 0) {
#pragma unroll
            for (int k = 0; k < 4; k++) {
                int R = r0 + (k >> 1) * 16 + (k & 1) * 8;
                red_s[cg][R] = sp[k];
                red_q[cg][R] = qp[k];
            }
        }
    }
    __syncthreads();   // red ready; all warps done reading A(h)
#pragma unroll
    for (int mb = 0; mb < 2; mb++)
#pragma unroll
        for (int h = 0; h < 2; h++) {
            int R = r0 + mb * 16 + h * 8;
            float S = red_s[0][R] + red_s[1][R] + red_s[2][R] + red_s[3][R];
            float Q = red_q[0][R] + red_q[1][R] + red_q[2][R] + red_q[3][R];
            float mu = S * 0.0078125f;
            float var = Q * 0.0078125f - mu * mu;
            float inv = rsqrtf(var + 1e-5f);
#pragma unroll
            for (int nb = 0; nb < 4; nb++) {
                int col = wC + c0l + nb * 8;
                float y0 = (C[mb][nb][2 * h + 0] - mu) * inv * s_g1[col] + s_e1[col];
                float y1v = (C[mb][nb][2 * h + 1] - mu) * inv * s_g1[col + 1] + s_e1[col + 1];
                Y[mb][nb][2 * h + 0] = y0;
                Y[mb][nb][2 * h + 1] = y1v;
                __nv_bfloat16 h0 = __float2bfloat16_rn(y0);
                __nv_bfloat16 h1 = __float2bfloat16_rn(y1v);
                __nv_bfloat162 HP; HP.x = h0; HP.y = h1;
                __nv_bfloat162 LP = __floats2bfloat162_rn(y0 - __bfloat162float(h0),
                                                          y1v - __bfloat162float(h1));
                uint32_t off = swoff(R, col);
                *(uint32_t*)(p_ahi + off) = *(uint32_t*)&HP;
                *(uint32_t*)(p_alo + off) = *(uint32_t*)&LP;
            }
        }
    CPWAITG(0);
    __syncthreads();

    // ---- FFN GEMM 1: y1(A) @ W1 ----
    ZEROC(C);
    gemm3(ab, ab + 16384, ab + 32768, ab + 65536, C, lane, wR, wC);
    __syncthreads();

    copyg(g_whi + w2m * 16384, p_whi, 2048);
    copyg(g_wlo + w2m * 16384, p_wlo, 2048);
    CPCOMMIT();

    // elu(C + b1) -> split into A (y1 kept in regs)
#pragma unroll
    for (int mb = 0; mb < 2; mb++)
#pragma unroll
        for (int nb = 0; nb < 4; nb++) {
            int col = wC + c0l + nb * 8;
#pragma unroll
            for (int h = 0; h < 2; h++) {
                int R = r0 + mb * 16 + h * 8;
                float t0 = C[mb][nb][2 * h + 0] + s_b1[col];
                float t1 = C[mb][nb][2 * h + 1] + s_b1[col + 1];
                t0 = t0 > 0.f ? t0 : expm1f(t0);
                t1 = t1 > 0.f ? t1 : expm1f(t1);
                __nv_bfloat16 h0 = __float2bfloat16_rn(t0);
                __nv_bfloat16 h1 = __float2bfloat16_rn(t1);
                __nv_bfloat162 HP; HP.x = h0; HP.y = h1;
                __nv_bfloat162 LP = __floats2bfloat162_rn(t0 - __bfloat162float(h0),
                                                          t1 - __bfloat162float(h1));
                uint32_t off = swoff(R, col);
                *(uint32_t*)(p_ahi + off) = *(uint32_t*)&HP;
                *(uint32_t*)(p_alo + off) = *(uint32_t*)&LP;
            }
        }
    CPWAITG(0);
    __syncthreads();

    // ---- FFN GEMM 2: elu(A) @ W2 ----
    ZEROC(C);
    gemm3(ab, ab + 16384, ab + 32768, ab + 65536, C, lane, wR, wC);

    // ---- LN2 (+ y1 residual from regs) ----
    {
        float sp[4], qp[4];
#pragma unroll
        for (int mb = 0; mb < 2; mb++)
#pragma unroll
            for (int h = 0; h < 2; h++) {
                float s = 0.f, q = 0.f;
#pragma unroll
                for (int nb = 0; nb < 4; nb++) {
                    int col = wC + c0l + nb * 8;
                    float v0 = C[mb][nb][2 * h + 0] + s_b2[col] + Y[mb][nb][2 * h + 0];
                    float v1 = C[mb][nb][2 * h + 1] + s_b2[col + 1] + Y[mb][nb][2 * h + 1];
                    C[mb][nb][2 * h + 0] = v0;
                    C[mb][nb][2 * h + 1] = v1;
                    s += v0 + v1;
                    q += v0 * v0 + v1 * v1;
                }
                sp[mb * 2 + h] = s; qp[mb * 2 + h] = q;
            }
#pragma unroll
        for (int k = 0; k < 4; k++) {
            sp[k] += __shfl_xor_sync(0xffffffffu, sp[k], 1);
            sp[k] += __shfl_xor_sync(0xffffffffu, sp[k], 2);
            qp[k] += __shfl_xor_sync(0xffffffffu, qp[k], 1);
            qp[k] += __shfl_xor_sync(0xffffffffu, qp[k], 2);
        }
        if ((lane & 3) == 0) {
#pragma unroll
            for (int k = 0; k < 4; k++) {
                int R = r0 + (k >> 1) * 16 + (k & 1) * 8;
                red_s[cg][R] = sp[k];
                red_q[cg][R] = qp[k];
            }
        }
    }
    __syncthreads();   // red ready; A/W dead
    float* stg = (float*)aptr;   // 64*132*4 = 33.8KB over A + 1KB of W
#pragma unroll
    for (int mb = 0; mb < 2; mb++)
#pragma unroll
        for (int h = 0; h < 2; h++) {
            int R = r0 + mb * 16 + h * 8;
            float S = red_s[0][R] + red_s[1][R] + red_s[2][R] + red_s[3][R];
            float Q = red_q[0][R] + red_q[1][R] + red_q[2][R] + red_q[3][R];
            float mu = S * 0.0078125f;
            float var = Q * 0.0078125f - mu * mu;
            float inv = rsqrtf(var + 1e-5f);
#pragma unroll
            for (int nb = 0; nb < 4; nb++) {
                int col = wC + c0l + nb * 8;
                float o0 = (C[mb][nb][2 * h + 0] - mu) * inv * s_g2[col] + s_e2[col];
                float o1 = (C[mb][nb][2 * h + 1] - mu) * inv * s_g2[col + 1] + s_e2[col + 1];
                *(float2*)(stg + R * 132 + col) = make_float2(o0, o1);
            }
        }
    __syncthreads();
    if (!last) {
#pragma unroll 2
        for (int i = tid; i < 2048; i += NTHR) {
            int row = i >> 5, c4 = i & 31;
            int nd = nbase + row;
            if (nd < NN) {
                float4 v = ((float4*)(stg + row * 132))[c4];
                uint2 h, l;
                split4(v, h, l);
                uint32_t off = (uint32_t)tile * 16384u + swoff(row, c4 * 4);
                *(uint2*)((char*)g_hshi + off) = h;
                *(uint2*)((char*)g_hslo + off) = l;
            }
        }
    } else {
        // final layer: per-graph partial sums (batch sorted); halves of 32 rows
        int f = tid & 127, q = tid >> 7;
        int rbeg = q * 32;
        int cur = s_batch[rbeg];
        float acc = 0.f;
#pragma unroll 4
        for (int r = rbeg; r < rbeg + 32; r++) {
            int bg = s_batch[r];
            if (bg < 0) break;
            if (bg != cur) {
                atomicAdd(&g_gm[cur * FD + f], acc);
                acc = 0.f;
                cur = bg;
            }
            acc += stg[r * 132 + f];
        }
        if (cur >= 0) atomicAdd(&g_gm[cur * FD + f], acc);
    }
}

// ===================== head =====================
__global__ void __launch_bounds__(128, 1) k_pool(
    const float* __restrict__ mdfW, const float* __restrict__ mdfb,
    const float* __restrict__ pg1, const float* __restrict__ pb1,
    const float* __restrict__ W1, const float* __restrict__ b1,
    const float* __restrict__ W2, const float* __restrict__ b2,
    const float* __restrict__ pg2, const float* __restrict__ pb2,
    float* __restrict__ out) {
    extern __shared__ float ws[];
    __shared__ float vm[128], hh[128], tt[128], red[8];
    int f = threadIdx.x, lane = f & 31, wp = f >> 5;
    for (int i = f; i < 16384; i += 128) {
        ws[i] = mdfW[i];
        ws[16384 + i] = W1[i];
        ws[32768 + i] = W2[i];
    }
    float c_mb = mdfb[f], c_g1 = pg1[f], c_b1 = pb1[f];
    float c_bl1 = b1[f], c_bl2 = b2[f], c_g2 = pg2[f], c_b2 = pb2[f];
    __syncthreads();
    for (int gi = 0; gi < 8; gi++) {
        int g = blockIdx.x * 8 + gi;
        vm[f] = g_gm[g * FD + f] / g_cntf[g];
        __syncthreads();
        float p = 0.f;
#pragma unroll 4
        for (int k = 0; k < 128; k++) p = fmaf(vm[k], ws[k * 128 + f], p);
        p += c_mb;
        float s = p, q = p * p;
#pragma unroll
        for (int off = 16; off; off >>= 1) {
            s += __shfl_xor_sync(0xffffffffu, s, off);
            q += __shfl_xor_sync(0xffffffffu, q, off);
        }
        if (lane == 0) { red[wp] = s; red[4 + wp] = q; }
        __syncthreads();
        s = red[0] + red[1] + red[2] + red[3];
        q = red[4] + red[5] + red[6] + red[7];
        float mu = s * 0.0078125f;
        float var = q * 0.0078125f - mu * mu;
        float inv = rsqrtf(var + 1e-5f);
        float h0 = (p - mu) * inv * c_g1 + c_b1;
        __syncthreads();
        hh[f] = h0;
        __syncthreads();
        float a = 0.f;
#pragma unroll 4
        for (int k = 0; k < 128; k++) a = fmaf(hh[k], ws[16384 + k * 128 + f], a);
        a += c_bl1;
        a = a > 0.f ? a : expm1f(a);
        tt[f] = a;
        __syncthreads();
        float y = 0.f;
#pragma unroll 4
        for (int k = 0; k < 128; k++) y = fmaf(tt[k], ws[32768 + k * 128 + f], y);
        y += c_bl2;
        float v2 = y + h0;
        s = v2; q = v2 * v2;
#pragma unroll
        for (int off = 16; off; off >>= 1) {
            s += __shfl_xor_sync(0xffffffffu, s, off);
            q += __shfl_xor_sync(0xffffffffu, q, off);
        }
        if (lane == 0) { red[wp] = s; red[4 + wp] = q; }
        __syncthreads();
        s = red[0] + red[1] + red[2] + red[3];
        q = red[4] + red[5] + red[6] + red[7];
        mu = s * 0.0078125f;
        var = q * 0.0078125f - mu * mu;
        inv = rsqrtf(var + 1e-5f);
        out[g * FD + f] = (v2 - mu) * inv * c_g2 + c_b2;
        __syncthreads();
    }
}

// ===================== launcher (setup-phase fork) =====================
extern "C" void kernel_launch(void* const* d_in, const int* in_sizes, int n_in,
                              void* d_out, int out_size) {
    const float* x    = (const float*)d_in[0];
    const float* w    = (const float*)d_in[1];
    const int*   ei   = (const int*)d_in[2];
    const int*   batch= (const int*)d_in[3];
    const float* Win  = (const float*)d_in[4];
    const float* bin  = (const float*)d_in[5];
    const float* sWl  = (const float*)d_in[6];
    const float* sbl  = (const float*)d_in[7];
    const float* sWr  = (const float*)d_in[8];
    const float* ln1g = (const float*)d_in[9];
    const float* ln1b = (const float*)d_in[10];
    const float* l1W  = (const float*)d_in[11];
    const float* l1b  = (const float*)d_in[12];
    const float* l2W  = (const float*)d_in[13];
    const float* l2b  = (const float*)d_in[14];
    const float* ln2g = (const float*)d_in[15];
    const float* ln2b = (const float*)d_in[16];
    const float* mdfW = (const float*)d_in[17];
    const float* mdfb = (const float*)d_in[18];
    const float* pg1  = (const float*)d_in[19];
    const float* pb1  = (const float*)d_in[20];
    const float* pW1  = (const float*)d_in[21];
    const float* pb1l = (const float*)d_in[22];
    const float* pW2  = (const float*)d_in[23];
    const float* pb2l = (const float*)d_in[24];
    const float* pg2  = (const float*)d_in[25];
    const float* pb2  = (const float*)d_in[26];

    const int SM_GEMM = 1024 + 98304;   // A(32K) + W(64K) + align
    const int SM_POOL = 49152 * 4;
    cudaFuncSetAttribute(k_input, cudaFuncAttributeMaxDynamicSharedMemorySize, SM_GEMM);
    cudaFuncSetAttribute(k_block, cudaFuncAttributeMaxDynamicSharedMemorySize, SM_GEMM);
    cudaFuncSetAttribute(k_pool,  cudaFuncAttributeMaxDynamicSharedMemorySize, SM_POOL);

    cudaStream_t s2;
    cudaStreamCreateWithFlags(&s2, cudaStreamNonBlocking);
    cudaEvent_t evFork, evCSR;
    cudaEventCreateWithFlags(&evFork, cudaEventDisableTiming);
    cudaEventCreateWithFlags(&evCSR, cudaEventDisableTiming);

    // fork: CSR build on s2, weights + input GEMM on stream0
    k_zero<<<512, 256>>>();
    cudaEventRecord(evFork, 0);
    cudaStreamWaitEvent(s2, evFork, 0);

    k_count<<<(NE + 255) / 256, 256, 0, s2>>>(ei, batch);
    k_scan1<<<(NN + 511) / 512, 512, 0, s2>>>();
    k_scan23<<<(NN + 255) / 256, 256, 0, s2>>>();
    k_fill<<<(NE + 255) / 256, 256, 0, s2>>>(ei);
    cudaEventRecord(evCSR, s2);

    k_wprep<<<dim3(64, 13), 256>>>(Win, sWl, sWr, l1W, l2W);
    k_input<<<NT2, NTHR, SM_GEMM>>>(x, w, Win, bin);
    cudaStreamWaitEvent(0, evCSR, 0);   // join before first gather

    for (int l = 0; l < 3; l++) {
        k_gather<<<(NN * 32 + 255) / 256, 256>>>();
        k_block<<<NT2, NTHR, SM_GEMM>>>(1 + l, 4 + l, 7 + l, 10 + l, (l == 2),
                                        batch,
                                        sbl + l * FD, l1b + l * FD, l2b + l * FD,
                                        ln1g + l * FD, ln1b + l * FD,
                                        ln2g + l * FD, ln2b + l * FD);
    }

    k_pool<<<NG / 8, 128, SM_POOL>>>(mdfW, mdfb, pg1, pb1, pW1, pb1l,
                                     pW2, pb2l, pg2, pb2, (float*)d_out);
}

// round 16
// speedup vs baseline: 1.3333x; 1.0234x over previous
#include <cuda_runtime.h>
#include <cuda_bf16.h>
#include <math.h>
#include <stdint.h>

#define NN 100000
#define NE 1600000
#define NG 1024
#define FD 128
#define TR 64               // tile rows
#define NT2 1563            // ceil(NN/64)
#define NTHR 256

// ===================== scratch (device globals) =====================
__device__ float g_degf[NN];
__device__ int   g_deg[NN];
__device__ int   g_rowstart[NN + 1];
__device__ int   g_cursor[NN];
__device__ int   g_csrsrc[NE];
__device__ int   g_cnti[NG];
__device__ float g_cntf[NG];
__device__ float g_gm[NG * FD];
__device__ int   g_bsum[256];
// split activations in 64-row tile-swizzled layout (16KB per tile per component)
__device__ __nv_bfloat16 g_agghi[NT2 * 8192];
__device__ __nv_bfloat16 g_agglo[NT2 * 8192];
__device__ __nv_bfloat16 g_hshi[NT2 * 8192];
__device__ __nv_bfloat16 g_hslo[NT2 * 8192];
// pre-transposed, split, swizzled weights: 13 matrices of 128x128 bf16
// m: 0=Win, 1..3=sage_Wl, 4..6=sage_Wr, 7..9=lin1, 10..12=lin2
__device__ __nv_bfloat16 g_whi[13 * 16384];
__device__ __nv_bfloat16 g_wlo[13 * 16384];

// ===================== helpers =====================
__device__ __forceinline__ uint32_t smem_u32(const void* p) {
    uint32_t a;
    asm("{ .reg .u64 t; cvta.to.shared.u64 t, %1; cvt.u32.u64 %0, t; }" : "=r"(a) : "l"(p));
    return a;
}

// XOR-swizzled byte offset inside a [rows][128 cols] bf16 tile (256B/row).
__device__ __forceinline__ uint32_t swoff(int row, int col) {
    return (uint32_t)row * 256u
         + ((uint32_t)(((col >> 3) ^ (row & 7)) & 15) << 4)
         + ((uint32_t)(col & 7) << 1);
}

#define LDM4(r0, r1, r2, r3, a) \
    asm volatile("ldmatrix.sync.aligned.m8n8.x4.shared.b16 {%0,%1,%2,%3}, [%4];" \
        : "=r"(r0), "=r"(r1), "=r"(r2), "=r"(r3) : "r"(a))

#define MMA16(c, a, b0, b1) \
    asm volatile("mma.sync.aligned.m16n8k16.row.col.f32.bf16.bf16.f32 " \
        "{%0,%1,%2,%3},{%4,%5,%6,%7},{%8,%9},{%0,%1,%2,%3};" \
        : "+f"((c)[0]), "+f"((c)[1]), "+f"((c)[2]), "+f"((c)[3]) \
        : "r"((a)[0]), "r"((a)[1]), "r"((a)[2]), "r"((a)[3]), "r"(b0), "r"(b1))

__device__ __forceinline__ void split4(float4 v, uint2& hi, uint2& lo) {
    __nv_bfloat16 hx = __float2bfloat16_rn(v.x), hy = __float2bfloat16_rn(v.y);
    __nv_bfloat16 hz = __float2bfloat16_rn(v.z), hw = __float2bfloat16_rn(v.w);
    float rx = v.x - __bfloat162float(hx), ry = v.y - __bfloat162float(hy);
    float rz = v.z - __bfloat162float(hz), rw = v.w - __bfloat162float(hw);
    __nv_bfloat162 H0; H0.x = hx; H0.y = hy;
    __nv_bfloat162 H1; H1.x = hz; H1.y = hw;
    __nv_bfloat162 L0 = __floats2bfloat162_rn(rx, ry);
    __nv_bfloat162 L1 = __floats2bfloat162_rn(rz, rw);
    hi.x = *(uint32_t*)&H0; hi.y = *(uint32_t*)&H1;
    lo.x = *(uint32_t*)&L0; lo.y = *(uint32_t*)&L1;
}

__device__ __forceinline__ float recon(const char* hi, const char* lo, uint32_t off,
                                       float& v1) {
    uint32_t uh = *(const uint32_t*)(hi + off);
    uint32_t ul = *(const uint32_t*)(lo + off);
    __nv_bfloat162 bh = *(__nv_bfloat162*)&uh;
    __nv_bfloat162 bl = *(__nv_bfloat162*)&ul;
    v1 = __bfloat162float(bh.y) + __bfloat162float(bl.y);
    return __bfloat162float(bh.x) + __bfloat162float(bl.x);
}

// fp32 global 64-row tile -> split bf16 swizzled smem (k_input only)
__device__ __forceinline__ void conv_tile(const float* __restrict__ src, int nbase,
                                          char* ahi, char* alo) {
#pragma unroll 2
    for (int i = threadIdx.x; i < 2048; i += NTHR) {
        int row = i >> 5, c4 = i & 31;
        int node = nbase + row;
        float4 v = make_float4(0.f, 0.f, 0.f, 0.f);
        if (node < NN) v = ((const float4*)src)[node * 32 + c4];
        uint2 h, l;
        split4(v, h, l);
        uint32_t off = swoff(row, c4 * 4);
        *(uint2*)(ahi + off) = h;
        *(uint2*)(alo + off) = l;
    }
}

// cp.async global -> smem (flat copy; layouts match)
__device__ __forceinline__ void copyg(const __nv_bfloat16* src, char* dst, int n16) {
    uint32_t d = smem_u32(dst);
    for (int i = threadIdx.x; i < n16; i += NTHR)
        asm volatile("cp.async.cg.shared.global [%0], [%1], 16;"
                     :: "r"(d + i * 16), "l"(src + i * 8) : "memory");
}
#define CPCOMMIT() asm volatile("cp.async.commit_group;" ::: "memory")
#define CPWAITG(n) asm volatile("cp.async.wait_group %0;" :: "n"(n) : "memory")

// warp-tiled 3-term split GEMM: C[32x32] += (Ahi+Alo)@(Whi+Wlo) (dropping lo*lo)
__device__ __forceinline__ void gemm3(uint32_t ahi, uint32_t alo,
                                      uint32_t whi, uint32_t wlo,
                                      float C[2][4][4], int lane, int wR, int wC) {
    int arow = (lane & 7) + ((lane >> 3) & 1) * 8;
    int acolo = ((lane >> 4) & 1) * 8;
    int brow = (lane & 7) + ((lane >> 4) & 1) * 8;
    int bcolo = ((lane >> 3) & 1) * 8;
#pragma unroll
    for (int kk = 0; kk < 8; kk++) {
        int kbase = kk * 16;
        uint32_t ah[2][4], al[2][4];
#pragma unroll
        for (int mb = 0; mb < 2; mb++) {
            uint32_t oa = swoff(wR + mb * 16 + arow, kbase + acolo);
            LDM4(ah[mb][0], ah[mb][1], ah[mb][2], ah[mb][3], ahi + oa);
            LDM4(al[mb][0], al[mb][1], al[mb][2], al[mb][3], alo + oa);
        }
#pragma unroll
        for (int nbp = 0; nbp < 2; nbp++) {
            uint32_t ob = swoff(wC + nbp * 16 + brow, kbase + bcolo);
            uint32_t bh[4], bl[4];
            LDM4(bh[0], bh[1], bh[2], bh[3], whi + ob);
            LDM4(bl[0], bl[1], bl[2], bl[3], wlo + ob);
#pragma unroll
            for (int mb = 0; mb < 2; mb++) {
                MMA16(C[mb][2 * nbp],     ah[mb], bh[0], bh[1]);
                MMA16(C[mb][2 * nbp + 1], ah[mb], bh[2], bh[3]);
                MMA16(C[mb][2 * nbp],     ah[mb], bl[0], bl[1]);
                MMA16(C[mb][2 * nbp + 1], ah[mb], bl[2], bl[3]);
                MMA16(C[mb][2 * nbp],     al[mb], bh[0], bh[1]);
                MMA16(C[mb][2 * nbp + 1], al[mb], bh[2], bh[3]);
            }
        }
    }
}

#define ZEROC(C) do { \
    _Pragma("unroll") for (int _a = 0; _a < 2; _a++) \
    _Pragma("unroll") for (int _b = 0; _b < 4; _b++) \
    _Pragma("unroll") for (int _c = 0; _c < 4; _c++) (C)[_a][_b][_c] = 0.f; \
} while (0)

// stage C frags into fp32 smem [64][132]
__device__ __forceinline__ void stageC(float* stg, float C[2][4][4], int lane, int wR, int wC) {
    int r0 = wR + (lane >> 2);
    int c0 = wC + (lane & 3) * 2;
#pragma unroll
    for (int mb = 0; mb < 2; mb++) {
#pragma unroll
        for (int nb = 0; nb < 4; nb++) {
            int row = r0 + mb * 16;
            int col = c0 + nb * 8;
            *(float2*)(stg + row * 132 + col) = make_float2(C[mb][nb][0], C[mb][nb][1]);
            *(float2*)(stg + (row + 8) * 132 + col) = make_float2(C[mb][nb][2], C[mb][nb][3]);
        }
    }
}

// ===================== setup kernels =====================
__global__ void k_zero() {
    int i = blockIdx.x * blockDim.x + threadIdx.x;
    if (i < NN) g_deg[i] = 0;
    if (i < NG) g_cnti[i] = 0;
}
__global__ void k_count(const int* __restrict__ ei, const int* __restrict__ batch) {
    int i = blockIdx.x * blockDim.x + threadIdx.x;
    if (i < NE) atomicAdd(&g_deg[ei[NE + i]], 1);
    if (i < NN) atomicAdd(&g_cnti[batch[i]], 1);
    if (i < NG * FD) g_gm[i] = 0.f;   // used only from layer-2 block onward
}
__global__ void k_scan1() {
    __shared__ int s[512];
    int i = blockIdx.x * 512 + threadIdx.x;
    int v = (i < NN) ? g_deg[i] : 0;
    s[threadIdx.x] = v;
    __syncthreads();
#pragma unroll
    for (int off = 1; off < 512; off <<= 1) {
        int t = (threadIdx.x >= off) ? s[threadIdx.x - off] : 0;
        __syncthreads();
        s[threadIdx.x] += t;
        __syncthreads();
    }
    if (i < NN) g_rowstart[i + 1] = s[threadIdx.x];
    if (threadIdx.x == 511) g_bsum[blockIdx.x] = s[511];
}
__global__ void k_scan23() {
    __shared__ int pre[256];
    const int nb = (NN + 511) / 512;  // 196
    int v = (threadIdx.x < nb) ? g_bsum[threadIdx.x] : 0;
    pre[threadIdx.x] = v;
    __syncthreads();
#pragma unroll
    for (int off = 1; off < 256; off <<= 1) {
        int t = (threadIdx.x >= off) ? pre[threadIdx.x - off] : 0;
        __syncthreads();
        pre[threadIdx.x] += t;
        __syncthreads();
    }
    pre[threadIdx.x] -= v;  // exclusive
    __syncthreads();
    int i = blockIdx.x * blockDim.x + threadIdx.x;
    if (i >= NN) return;
    int r = g_rowstart[i + 1] + pre[i >> 9];
    g_rowstart[i + 1] = r;
    g_cursor[i] = r - g_deg[i];
    g_degf[i] = fmaxf((float)g_deg[i], 1.f);
    if (i == 0) g_rowstart[0] = 0;
    if (i < NG) g_cntf[i] = fmaxf((float)g_cnti[i], 1.f);
}
__global__ void k_fill(const int* __restrict__ ei) {
    int e = blockIdx.x * blockDim.x + threadIdx.x;
    if (e >= NE) return;
    int src = ei[e];
    int dst = ei[NE + e];
    int pos = atomicAdd(&g_cursor[dst], 1);
    g_csrsrc[pos] = src;
}
// gather: 16 lanes per node, one 16B granule per lane per edge (halved instructions).
__global__ void k_gather() {
    int t = blockIdx.x * blockDim.x + threadIdx.x;
    int gw = t >> 4;
    int sl = t & 15;                 // logical 16B granule (8 cols) this lane owns
    if (gw >= NN) return;
    int beg = g_rowstart[gw], end = g_rowstart[gw + 1];
    float acc[8];
#pragma unroll
    for (int k = 0; k < 8; k++) acc[k] = 0.f;
    const char* hs = (const char*)g_hshi;
    int e = beg;
    for (; e + 4 <= end; e += 4) {
#pragma unroll
        for (int j = 0; j < 4; j++) {
            int s = g_csrsrc[e + j];
            uint32_t off = ((uint32_t)(s >> 6)) * 16384u + (uint32_t)(s & 63) * 256u
                         + (uint32_t)(((sl ^ (s & 7)) & 15) << 4);
            uint4 u = *(const uint4*)(hs + off);
            float2 a = __bfloat1622float2(*(__nv_bfloat162*)&u.x);
            float2 b = __bfloat1622float2(*(__nv_bfloat162*)&u.y);
            float2 c = __bfloat1622float2(*(__nv_bfloat162*)&u.z);
            float2 d = __bfloat1622float2(*(__nv_bfloat162*)&u.w);
            acc[0] += a.x; acc[1] += a.y; acc[2] += b.x; acc[3] += b.y;
            acc[4] += c.x; acc[5] += c.y; acc[6] += d.x; acc[7] += d.y;
        }
    }
    for (; e < end; ++e) {
        int s = g_csrsrc[e];
        uint32_t off = ((uint32_t)(s >> 6)) * 16384u + (uint32_t)(s & 63) * 256u
                     + (uint32_t)(((sl ^ (s & 7)) & 15) << 4);
        uint4 u = *(const uint4*)(hs + off);
        float2 a = __bfloat1622float2(*(__nv_bfloat162*)&u.x);
        float2 b = __bfloat1622float2(*(__nv_bfloat162*)&u.y);
        float2 c = __bfloat1622float2(*(__nv_bfloat162*)&u.z);
        float2 d = __bfloat1622float2(*(__nv_bfloat162*)&u.w);
        acc[0] += a.x; acc[1] += a.y; acc[2] += b.x; acc[3] += b.y;
        acc[4] += c.x; acc[5] += c.y; acc[6] += d.x; acc[7] += d.y;
    }
    float inv = 1.f / g_degf[gw];
#pragma unroll
    for (int k = 0; k < 8; k++) acc[k] *= inv;
    uint2 h0, l0, h1, l1;
    split4(make_float4(acc[0], acc[1], acc[2], acc[3]), h0, l0);
    split4(make_float4(acc[4], acc[5], acc[6], acc[7]), h1, l1);
    uint4 H; H.x = h0.x; H.y = h0.y; H.z = h1.x; H.w = h1.y;
    uint4 L; L.x = l0.x; L.y = l0.y; L.z = l1.x; L.w = l1.y;
    int row = gw & 63;
    uint32_t woff = ((uint32_t)(gw >> 6)) * 16384u + (uint32_t)row * 256u
                  + (uint32_t)(((sl ^ (row & 7)) & 15) << 4);
    *(uint4*)((char*)g_agghi + woff) = H;
    *(uint4*)((char*)g_agglo + woff) = L;
}
// weight prep: transpose to [N,K], split hi/lo bf16, swizzled (13 matrices)
__global__ void k_wprep(const float* __restrict__ Win, const float* __restrict__ sWl,
                        const float* __restrict__ sWr, const float* __restrict__ l1W,
                        const float* __restrict__ l2W) {
    int m = blockIdx.y;
    int idx = blockIdx.x * 256 + threadIdx.x;
    if (idx >= 16384) return;
    int n = idx >> 7, k = idx & 127;
    float v;
    if (m == 0)       v = Win[k * 128 + n];
    else if (m < 4)   v = sWl[(m - 1) * 16384 + k * 128 + n];
    else if (m < 7)   v = sWr[(m - 4) * 16384 + k * 128 + n];
    else if (m < 10)  v = l1W[(m - 7) * 16384 + k * 128 + n];
    else              v = l2W[(m - 10) * 16384 + k * 128 + n];
    __nv_bfloat16 hi = __float2bfloat16_rn(v);
    float r = v - __bfloat162float(hi);
    __nv_bfloat16 lo = __float2bfloat16_rn(r);
    uint32_t e = swoff(n, k) >> 1;
    g_whi[m * 16384 + e] = hi;
    g_wlo[m * 16384 + e] = lo;
}

// smem layout (both GEMM kernels): A_hi@0(16K) A_lo@16K W_hi@32K(32K) W_lo@64K(32K)
// ===================== input GEMM: h = [x|w] @ W_in + b_in =====================
__global__ void __launch_bounds__(NTHR, 2) k_input(
    const float* __restrict__ x, const float* __restrict__ w,
    const float* __restrict__ Win, const float* __restrict__ bin) {
    extern __shared__ char dsm[];
    __shared__ float s_b[128], s_wr[128];
    uint32_t base = smem_u32(dsm);
    uint32_t ab = (base + 1023) & ~1023u;
    char* aptr = dsm + (ab - base);
    int tid = threadIdx.x;
    int lane = tid & 31, wid = tid >> 5;
    int wR = (wid >> 2) * 32, wC = (wid & 3) * 32;
    if (tid < 128) { s_b[tid] = bin[tid]; s_wr[tid] = Win[128 * 128 + tid]; }
    copyg(g_whi, aptr + 32768, 2048);
    copyg(g_wlo, aptr + 65536, 2048);
    CPCOMMIT();
    int tile = blockIdx.x;
    int nbase = tile * TR;
    conv_tile(x, nbase, aptr, aptr + 16384);
    CPWAITG(0);
    __syncthreads();
    float C[2][4][4];
    ZEROC(C);
    gemm3(ab, ab + 16384, ab + 32768, ab + 65536, C, lane, wR, wC);
    __syncthreads();
    float* stg = (float*)aptr;
    stageC(stg, C, lane, wR, wC);
    __syncthreads();
#pragma unroll 2
    for (int i = tid; i < 2048; i += NTHR) {
        int row = i >> 5, c4 = i & 31;
        int nd = nbase + row;
        if (nd < NN) {
            float wn = w[nd];
            float4 v = ((float4*)(stg + row * 132))[c4];
            float4 o;
            o.x = v.x + s_b[c4 * 4 + 0] + wn * s_wr[c4 * 4 + 0];
            o.y = v.y + s_b[c4 * 4 + 1] + wn * s_wr[c4 * 4 + 1];
            o.z = v.z + s_b[c4 * 4 + 2] + wn * s_wr[c4 * 4 + 2];
            o.w = v.w + s_b[c4 * 4 + 3] + wn * s_wr[c4 * 4 + 3];
            uint2 h, l;
            split4(o, h, l);
            uint32_t off = (uint32_t)tile * 16384u + swoff(row, c4 * 4);
            *(uint2*)((char*)g_hshi + off) = h;
            *(uint2*)((char*)g_hslo + off) = l;
        }
    }
}

// ===================== fused sage+FFN block (64-row tiles, occ 2) ==============
__global__ void __launch_bounds__(NTHR, 2) k_block(
    int wlm, int wrm, int w1m, int w2m, int last,
    const int* __restrict__ batch,
    const float* __restrict__ bl, const float* __restrict__ b1,
    const float* __restrict__ b2,
    const float* __restrict__ g1, const float* __restrict__ e1,
    const float* __restrict__ g2, const float* __restrict__ e2) {
    extern __shared__ char dsm[];
    __shared__ float s_bl[128], s_b1[128], s_b2[128];
    __shared__ float s_g1[128], s_e1[128], s_g2[128], s_e2[128];
    __shared__ float red_s[4][64], red_q[4][64];
    __shared__ int s_batch[64];
    uint32_t base = smem_u32(dsm);
    uint32_t ab = (base + 1023) & ~1023u;
    char* aptr = dsm + (ab - base);
    char* p_ahi = aptr;
    char* p_alo = aptr + 16384;
    char* p_whi = aptr + 32768;
    char* p_wlo = aptr + 65536;
    int tid = threadIdx.x, lane = tid & 31, wid = tid >> 5;
    int wR = (wid >> 2) * 32, wC = (wid & 3) * 32;
    int cg = wid & 3;
    int r0 = wR + (lane >> 2);
    int c0l = (lane & 3) * 2;
    int tile = blockIdx.x;
    int nbase = tile * TR;

    copyg(g_agghi + tile * 8192, p_ahi, 1024);
    copyg(g_agglo + tile * 8192, p_alo, 1024);
    copyg(g_whi + wlm * 16384, p_whi, 2048);
    copyg(g_wlo + wlm * 16384, p_wlo, 2048);
    CPCOMMIT();
    if (tid < 128) {
        s_bl[tid] = bl[tid]; s_b1[tid] = b1[tid]; s_b2[tid] = b2[tid];
        s_g1[tid] = g1[tid]; s_e1[tid] = e1[tid];
        s_g2[tid] = g2[tid]; s_e2[tid] = e2[tid];
    }
    if (last && tid < 64) {
        int nd = nbase + tid;
        s_batch[tid] = (nd < NN) ? batch[nd] : -1;
    }
    CPWAITG(0);
    __syncthreads();

    // ---- sage GEMM 1: agg(A) @ Wl ----
    float C[2][4][4];
    ZEROC(C);
    gemm3(ab, ab + 16384, ab + 32768, ab + 65536, C, lane, wR, wC);
    __syncthreads();

    // ---- load h -> A, Wr -> W; sage GEMM 2 accumulate ----
    copyg(g_hshi + tile * 8192, p_ahi, 1024);
    copyg(g_hslo + tile * 8192, p_alo, 1024);
    copyg(g_whi + wrm * 16384, p_whi, 2048);
    copyg(g_wlo + wrm * 16384, p_wlo, 2048);
    CPCOMMIT();
    CPWAITG(0);
    __syncthreads();
    gemm3(ab, ab + 16384, ab + 32768, ab + 65536, C, lane, wR, wC);
    __syncthreads();

    // prefetch W1 under LN1
    copyg(g_whi + w1m * 16384, p_whi, 2048);
    copyg(g_wlo + w1m * 16384, p_wlo, 2048);
    CPCOMMIT();

    // ---- LN1 (+ h residual from A split), save y1 frag in regs, y1 -> A ----
    float Y[2][4][4];
    {
        float sp[4], qp[4];
#pragma unroll
        for (int mb = 0; mb < 2; mb++)
#pragma unroll
            for (int h = 0; h < 2; h++) {
                int R = r0 + mb * 16 + h * 8;
                float s = 0.f, q = 0.f;
#pragma unroll
                for (int nb = 0; nb < 4; nb++) {
                    int col = wC + c0l + nb * 8;
                    float h1;
                    float h0 = recon(p_ahi, p_alo, swoff(R, col), h1);
                    float v0 = C[mb][nb][2 * h + 0] + s_bl[col] + h0;
                    float v1 = C[mb][nb][2 * h + 1] + s_bl[col + 1] + h1;
                    C[mb][nb][2 * h + 0] = v0;
                    C[mb][nb][2 * h + 1] = v1;
                    s += v0 + v1;
                    q += v0 * v0 + v1 * v1;
                }
                sp[mb * 2 + h] = s; qp[mb * 2 + h] = q;
            }
#pragma unroll
        for (int k = 0; k < 4; k++) {
            sp[k] += __shfl_xor_sync(0xffffffffu, sp[k], 1);
            sp[k] += __shfl_xor_sync(0xffffffffu, sp[k], 2);
            qp[k] += __shfl_xor_sync(0xffffffffu, qp[k], 1);
            qp[k] += __shfl_xor_sync(0xffffffffu, qp[k], 2);
        }
        if ((lane & 3) == 0) {
#pragma unroll
            for (int k = 0; k < 4; k++) {
                int R = r0 + (k >> 1) * 16 + (k & 1) * 8;
                red_s[cg][R] = sp[k];
                red_q[cg][R] = qp[k];
            }
        }
    }
    __syncthreads();   // red ready; all warps done reading A(h)
#pragma unroll
    for (int mb = 0; mb < 2; mb++)
#pragma unroll
        for (int h = 0; h < 2; h++) {
            int R = r0 + mb * 16 + h * 8;
            float S = red_s[0][R] + red_s[1][R] + red_s[2][R] + red_s[3][R];
            float Q = red_q[0][R] + red_q[1][R] + red_q[2][R] + red_q[3][R];
            float mu = S * 0.0078125f;
            float var = Q * 0.0078125f - mu * mu;
            float inv = rsqrtf(var + 1e-5f);
#pragma unroll
            for (int nb = 0; nb < 4; nb++) {
                int col = wC + c0l + nb * 8;
                float y0 = (C[mb][nb][2 * h + 0] - mu) * inv * s_g1[col] + s_e1[col];
                float y1v = (C[mb][nb][2 * h + 1] - mu) * inv * s_g1[col + 1] + s_e1[col + 1];
                Y[mb][nb][2 * h + 0] = y0;
                Y[mb][nb][2 * h + 1] = y1v;
                __nv_bfloat16 h0 = __float2bfloat16_rn(y0);
                __nv_bfloat16 h1 = __float2bfloat16_rn(y1v);
                __nv_bfloat162 HP; HP.x = h0; HP.y = h1;
                __nv_bfloat162 LP = __floats2bfloat162_rn(y0 - __bfloat162float(h0),
                                                          y1v - __bfloat162float(h1));
                uint32_t off = swoff(R, col);
                *(uint32_t*)(p_ahi + off) = *(uint32_t*)&HP;
                *(uint32_t*)(p_alo + off) = *(uint32_t*)&LP;
            }
        }
    CPWAITG(0);
    __syncthreads();

    // ---- FFN GEMM 1: y1(A) @ W1 ----
    ZEROC(C);
    gemm3(ab, ab + 16384, ab + 32768, ab + 65536, C, lane, wR, wC);
    __syncthreads();

    copyg(g_whi + w2m * 16384, p_whi, 2048);
    copyg(g_wlo + w2m * 16384, p_wlo, 2048);
    CPCOMMIT();

    // elu(C + b1) -> split into A (y1 kept in regs)
#pragma unroll
    for (int mb = 0; mb < 2; mb++)
#pragma unroll
        for (int nb = 0; nb < 4; nb++) {
            int col = wC + c0l + nb * 8;
#pragma unroll
            for (int h = 0; h < 2; h++) {
                int R = r0 + mb * 16 + h * 8;
                float t0 = C[mb][nb][2 * h + 0] + s_b1[col];
                float t1 = C[mb][nb][2 * h + 1] + s_b1[col + 1];
                t0 = t0 > 0.f ? t0 : expm1f(t0);
                t1 = t1 > 0.f ? t1 : expm1f(t1);
                __nv_bfloat16 h0 = __float2bfloat16_rn(t0);
                __nv_bfloat16 h1 = __float2bfloat16_rn(t1);
                __nv_bfloat162 HP; HP.x = h0; HP.y = h1;
                __nv_bfloat162 LP = __floats2bfloat162_rn(t0 - __bfloat162float(h0),
                                                          t1 - __bfloat162float(h1));
                uint32_t off = swoff(R, col);
                *(uint32_t*)(p_ahi + off) = *(uint32_t*)&HP;
                *(uint32_t*)(p_alo + off) = *(uint32_t*)&LP;
            }
        }
    CPWAITG(0);
    __syncthreads();

    // ---- FFN GEMM 2: elu(A) @ W2 ----
    ZEROC(C);
    gemm3(ab, ab + 16384, ab + 32768, ab + 65536, C, lane, wR, wC);

    // ---- LN2 (+ y1 residual from regs) ----
    {
        float sp[4], qp[4];
#pragma unroll
        for (int mb = 0; mb < 2; mb++)
#pragma unroll
            for (int h = 0; h < 2; h++) {
                float s = 0.f, q = 0.f;
#pragma unroll
                for (int nb = 0; nb < 4; nb++) {
                    int col = wC + c0l + nb * 8;
                    float v0 = C[mb][nb][2 * h + 0] + s_b2[col] + Y[mb][nb][2 * h + 0];
                    float v1 = C[mb][nb][2 * h + 1] + s_b2[col + 1] + Y[mb][nb][2 * h + 1];
                    C[mb][nb][2 * h + 0] = v0;
                    C[mb][nb][2 * h + 1] = v1;
                    s += v0 + v1;
                    q += v0 * v0 + v1 * v1;
                }
                sp[mb * 2 + h] = s; qp[mb * 2 + h] = q;
            }
#pragma unroll
        for (int k = 0; k < 4; k++) {
            sp[k] += __shfl_xor_sync(0xffffffffu, sp[k], 1);
            sp[k] += __shfl_xor_sync(0xffffffffu, sp[k], 2);
            qp[k] += __shfl_xor_sync(0xffffffffu, qp[k], 1);
            qp[k] += __shfl_xor_sync(0xffffffffu, qp[k], 2);
        }
        if ((lane & 3) == 0) {
#pragma unroll
            for (int k = 0; k < 4; k++) {
                int R = r0 + (k >> 1) * 16 + (k & 1) * 8;
                red_s[cg][R] = sp[k];
                red_q[cg][R] = qp[k];
            }
        }
    }
    __syncthreads();   // red ready
    if (!last) {
        // direct register -> global split write (no staging)
        char* dsthi = (char*)g_hshi + (uint32_t)tile * 16384u;
        char* dstlo = (char*)g_hslo + (uint32_t)tile * 16384u;
#pragma unroll
        for (int mb = 0; mb < 2; mb++)
#pragma unroll
            for (int h = 0; h < 2; h++) {
                int R = r0 + mb * 16 + h * 8;
                float S = red_s[0][R] + red_s[1][R] + red_s[2][R] + red_s[3][R];
                float Q = red_q[0][R] + red_q[1][R] + red_q[2][R] + red_q[3][R];
                float mu = S * 0.0078125f;
                float var = Q * 0.0078125f - mu * mu;
                float inv = rsqrtf(var + 1e-5f);
                bool ok = (nbase + R) < NN;
#pragma unroll
                for (int nb = 0; nb < 4; nb++) {
                    int col = wC + c0l + nb * 8;
                    float o0 = (C[mb][nb][2 * h + 0] - mu) * inv * s_g2[col] + s_e2[col];
                    float o1 = (C[mb][nb][2 * h + 1] - mu) * inv * s_g2[col + 1] + s_e2[col + 1];
                    __nv_bfloat16 h0 = __float2bfloat16_rn(o0);
                    __nv_bfloat16 h1 = __float2bfloat16_rn(o1);
                    __nv_bfloat162 HP; HP.x = h0; HP.y = h1;
                    __nv_bfloat162 LP = __floats2bfloat162_rn(o0 - __bfloat162float(h0),
                                                              o1 - __bfloat162float(h1));
                    if (ok) {
                        uint32_t off = swoff(R, col);
                        *(uint32_t*)(dsthi + off) = *(uint32_t*)&HP;
                        *(uint32_t*)(dstlo + off) = *(uint32_t*)&LP;
                    }
                }
            }
    } else {
        // final layer: stage fp32, then per-graph partial sums (batch sorted)
        float* stg = (float*)aptr;   // A/W dead
#pragma unroll
        for (int mb = 0; mb < 2; mb++)
#pragma unroll
            for (int h = 0; h < 2; h++) {
                int R = r0 + mb * 16 + h * 8;
                float S = red_s[0][R] + red_s[1][R] + red_s[2][R] + red_s[3][R];
                float Q = red_q[0][R] + red_q[1][R] + red_q[2][R] + red_q[3][R];
                float mu = S * 0.0078125f;
                float var = Q * 0.0078125f - mu * mu;
                float inv = rsqrtf(var + 1e-5f);
#pragma unroll
                for (int nb = 0; nb < 4; nb++) {
                    int col = wC + c0l + nb * 8;
                    float o0 = (C[mb][nb][2 * h + 0] - mu) * inv * s_g2[col] + s_e2[col];
                    float o1 = (C[mb][nb][2 * h + 1] - mu) * inv * s_g2[col + 1] + s_e2[col + 1];
                    *(float2*)(stg + R * 132 + col) = make_float2(o0, o1);
                }
            }
        __syncthreads();
        int f = tid & 127, q = tid >> 7;
        int rbeg = q * 32;
        int cur = s_batch[rbeg];
        float acc = 0.f;
#pragma unroll 4
        for (int r = rbeg; r < rbeg + 32; r++) {
            int bg = s_batch[r];
            if (bg < 0) break;
            if (bg != cur) {
                atomicAdd(&g_gm[cur * FD + f], acc);
                acc = 0.f;
                cur = bg;
            }
            acc += stg[r * 132 + f];
        }
        if (cur >= 0) atomicAdd(&g_gm[cur * FD + f], acc);
    }
}

// ===================== head =====================
__global__ void __launch_bounds__(128, 1) k_pool(
    const float* __restrict__ mdfW, const float* __restrict__ mdfb,
    const float* __restrict__ pg1, const float* __restrict__ pb1,
    const float* __restrict__ W1, const float* __restrict__ b1,
    const float* __restrict__ W2, const float* __restrict__ b2,
    const float* __restrict__ pg2, const float* __restrict__ pb2,
    float* __restrict__ out) {
    extern __shared__ float ws[];
    __shared__ float vm[128], hh[128], tt[128], red[8];
    int f = threadIdx.x, lane = f & 31, wp = f >> 5;
    for (int i = f; i < 16384; i += 128) {
        ws[i] = mdfW[i];
        ws[16384 + i] = W1[i];
        ws[32768 + i] = W2[i];
    }
    float c_mb = mdfb[f], c_g1 = pg1[f], c_b1 = pb1[f];
    float c_bl1 = b1[f], c_bl2 = b2[f], c_g2 = pg2[f], c_b2 = pb2[f];
    __syncthreads();
    for (int gi = 0; gi < 8; gi++) {
        int g = blockIdx.x * 8 + gi;
        vm[f] = g_gm[g * FD + f] / g_cntf[g];
        __syncthreads();
        float p = 0.f;
#pragma unroll 4
        for (int k = 0; k < 128; k++) p = fmaf(vm[k], ws[k * 128 + f], p);
        p += c_mb;
        float s = p, q = p * p;
#pragma unroll
        for (int off = 16; off; off >>= 1) {
            s += __shfl_xor_sync(0xffffffffu, s, off);
            q += __shfl_xor_sync(0xffffffffu, q, off);
        }
        if (lane == 0) { red[wp] = s; red[4 + wp] = q; }
        __syncthreads();
        s = red[0] + red[1] + red[2] + red[3];
        q = red[4] + red[5] + red[6] + red[7];
        float mu = s * 0.0078125f;
        float var = q * 0.0078125f - mu * mu;
        float inv = rsqrtf(var + 1e-5f);
        float h0 = (p - mu) * inv * c_g1 + c_b1;
        __syncthreads();
        hh[f] = h0;
        __syncthreads();
        float a = 0.f;
#pragma unroll 4
        for (int k = 0; k < 128; k++) a = fmaf(hh[k], ws[16384 + k * 128 + f], a);
        a += c_bl1;
        a = a > 0.f ? a : expm1f(a);
        tt[f] = a;
        __syncthreads();
        float y = 0.f;
#pragma unroll 4
        for (int k = 0; k < 128; k++) y = fmaf(tt[k], ws[32768 + k * 128 + f], y);
        y += c_bl2;
        float v2 = y + h0;
        s = v2; q = v2 * v2;
#pragma unroll
        for (int off = 16; off; off >>= 1) {
            s += __shfl_xor_sync(0xffffffffu, s, off);
            q += __shfl_xor_sync(0xffffffffu, q, off);
        }
        if (lane == 0) { red[wp] = s; red[4 + wp] = q; }
        __syncthreads();
        s = red[0] + red[1] + red[2] + red[3];
        q = red[4] + red[5] + red[6] + red[7];
        mu = s * 0.0078125f;
        var = q * 0.0078125f - mu * mu;
        inv = rsqrtf(var + 1e-5f);
        out[g * FD + f] = (v2 - mu) * inv * c_g2 + c_b2;
        __syncthreads();
    }
}

// ===================== launcher (setup-phase fork) =====================
extern "C" void kernel_launch(void* const* d_in, const int* in_sizes, int n_in,
                              void* d_out, int out_size) {
    const float* x    = (const float*)d_in[0];
    const float* w    = (const float*)d_in[1];
    const int*   ei   = (const int*)d_in[2];
    const int*   batch= (const int*)d_in[3];
    const float* Win  = (const float*)d_in[4];
    const float* bin  = (const float*)d_in[5];
    const float* sWl  = (const float*)d_in[6];
    const float* sbl  = (const float*)d_in[7];
    const float* sWr  = (const float*)d_in[8];
    const float* ln1g = (const float*)d_in[9];
    const float* ln1b = (const float*)d_in[10];
    const float* l1W  = (const float*)d_in[11];
    const float* l1b  = (const float*)d_in[12];
    const float* l2W  = (const float*)d_in[13];
    const float* l2b  = (const float*)d_in[14];
    const float* ln2g = (const float*)d_in[15];
    const float* ln2b = (const float*)d_in[16];
    const float* mdfW = (const float*)d_in[17];
    const float* mdfb = (const float*)d_in[18];
    const float* pg1  = (const float*)d_in[19];
    const float* pb1  = (const float*)d_in[20];
    const float* pW1  = (const float*)d_in[21];
    const float* pb1l = (const float*)d_in[22];
    const float* pW2  = (const float*)d_in[23];
    const float* pb2l = (const float*)d_in[24];
    const float* pg2  = (const float*)d_in[25];
    const float* pb2  = (const float*)d_in[26];

    const int SM_GEMM = 1024 + 98304;   // A(32K) + W(64K) + align
    const int SM_POOL = 49152 * 4;
    cudaFuncSetAttribute(k_input, cudaFuncAttributeMaxDynamicSharedMemorySize, SM_GEMM);
    cudaFuncSetAttribute(k_block, cudaFuncAttributeMaxDynamicSharedMemorySize, SM_GEMM);
    cudaFuncSetAttribute(k_pool,  cudaFuncAttributeMaxDynamicSharedMemorySize, SM_POOL);

    cudaStream_t s2;
    cudaStreamCreateWithFlags(&s2, cudaStreamNonBlocking);
    cudaEvent_t evFork, evCSR;
    cudaEventCreateWithFlags(&evFork, cudaEventDisableTiming);
    cudaEventCreateWithFlags(&evCSR, cudaEventDisableTiming);

    // fork: CSR build on s2, weights + input GEMM on stream0
    k_zero<<<(NN + 255) / 256, 256>>>();
    cudaEventRecord(evFork, 0);
    cudaStreamWaitEvent(s2, evFork, 0);

    k_count<<<(NE + 255) / 256, 256, 0, s2>>>(ei, batch);
    k_scan1<<<(NN + 511) / 512, 512, 0, s2>>>();
    k_scan23<<<(NN + 255) / 256, 256, 0, s2>>>();
    k_fill<<<(NE + 255) / 256, 256, 0, s2>>>(ei);
    cudaEventRecord(evCSR, s2);

    k_wprep<<<dim3(64, 13), 256>>>(Win, sWl, sWr, l1W, l2W);
    k_input<<<NT2, NTHR, SM_GEMM>>>(x, w, Win, bin);
    cudaStreamWaitEvent(0, evCSR, 0);   // join before first gather

    for (int l = 0; l < 3; l++) {
        k_gather<<<(NN * 16 + 255) / 256, 256>>>();
        k_block<<<NT2, NTHR, SM_GEMM>>>(1 + l, 4 + l, 7 + l, 10 + l, (l == 2),
                                        batch,
                                        sbl + l * FD, l1b + l * FD, l2b + l * FD,
                                        ln1g + l * FD, ln1b + l * FD,
                                        ln2g + l * FD, ln2b + l * FD);
    }

    k_pool<<<NG / 8, 128, SM_POOL>>>(mdfW, mdfb, pg1, pb1, pW1, pb1l,
                                     pW2, pb2l, pg2, pb2, (float*)d_out);
}